// round 11
// baseline (speedup 1.0000x reference)
#include <cuda_runtime.h>
#include <cuda_bf16.h>
#include <cstdint>

// ---------------------------------------------------------------------------
// SpatialConvModule (SCNN-style): 4 directional recurrent 3-tap convs + fusion
// B=8, C=128, H=W=160. All fp32, packed f32x2 FMA (sm_103a).
// R11: 256-thread pre/step4 (halved per-thread acc, doubled warps/block),
//      coalesced step staging, launch order tuned for ncu -s 5 window.
// ---------------------------------------------------------------------------

#define EPSV 1e-5f
#define SPAT 25600            // 160*160

// ---- static device scratch (allocation-free rule) -------------------------
__device__ float  g_pre [4ull*8*128*160*160];  // pre-activations (read-only in steps)
__device__ float  g_feat[4ull*8*128*160*160];  // recurrence outputs (features)
__device__ float  g_xT [8ull*128*160*160];     // x transposed per (b,c): [w][h]
__device__ float  g_tmp[2ull*8*128*160*160];   // dirs 2,3 feat transposed back
__device__ float2 g_wkp[4*64*3*128];           // [dir][cpair][tap][o] (even,odd c)
__device__ float2 g_wfp[256*128];              // [qpair][o], pre-scaled by fbn inv
__device__ float  g_s[512], g_sh[512], g_fc[128];

// packed fp32x2 fma: d = a*b + c (elementwise on both halves)
__device__ __forceinline__ float2 ffma2f(float2 a, float2 b, float2 c) {
    float2 d;
    asm("fma.rn.f32x2 %0, %1, %2, %3;"
        : "=l"(reinterpret_cast<unsigned long long&>(d))
        : "l"(reinterpret_cast<unsigned long long&>(a)),
          "l"(reinterpret_cast<unsigned long long&>(b)),
          "l"(reinterpret_cast<unsigned long long&>(c)));
    return d;
}

__global__ void noop_kernel() {}

// ---------------------------------------------------------------------------
// Prep: repack conv weights to [dir][cpair][tap][o] float2, fold BN into
// scale/shift, pre-scale fusion weights by fused-BN inv.
// ---------------------------------------------------------------------------
__global__ void prep_kernel(const float* __restrict__ kern,
                            const float* __restrict__ bg, const float* __restrict__ bb,
                            const float* __restrict__ bm, const float* __restrict__ bv,
                            const float* __restrict__ fw, const float* __restrict__ fb,
                            const float* __restrict__ fg, const float* __restrict__ fbeta,
                            const float* __restrict__ fm, const float* __restrict__ fv) {
    const int NWK = 98304, NWF = 32768;
    int total = NWK + NWF + 512 + 128;
    for (int i = blockIdx.x * blockDim.x + threadIdx.x; i < total;
         i += gridDim.x * blockDim.x) {
        if (i < NWK) {
            int dir = i / 24576; int r = i % 24576;
            int cp = r / 384;    int r2 = r % 384;
            int d = r2 / 128;    int o = r2 % 128;
            int c0 = 2 * cp;
            float a0, a1;
            if (dir < 2) {  // 1x3 kernel: kh=1, kw=d
                a0 = kern[(((dir*128 + o)*128 + c0    )*3 + 1)*3 + d];
                a1 = kern[(((dir*128 + o)*128 + c0 + 1)*3 + 1)*3 + d];
            } else {        // 3x1 kernel: kh=d, kw=1
                a0 = kern[(((dir*128 + o)*128 + c0    )*3 + d)*3 + 1];
                a1 = kern[(((dir*128 + o)*128 + c0 + 1)*3 + d)*3 + 1];
            }
            g_wkp[i] = make_float2(a0, a1);
        } else if (i < NWK + NWF) {
            int idx = i - NWK; int qp = idx / 128; int o = idx % 128;
            float fs = fg[o] * rsqrtf(fv[o] + EPSV);
            g_wfp[idx] = make_float2(fw[o*512 + 2*qp] * fs, fw[o*512 + 2*qp + 1] * fs);
        } else if (i < NWK + NWF + 512) {
            int idx = i - NWK - NWF;
            float s = bg[idx] * rsqrtf(bv[idx] + EPSV);
            g_s[idx] = s; g_sh[idx] = bb[idx] - bm[idx] * s;
        } else {
            int o = i - NWK - NWF - 512;
            float fs = fg[o] * rsqrtf(fv[o] + EPSV);
            g_fc[o] = fb[o] * fs + fbeta[o] - fm[o] * fs;
        }
    }
}

// ---------------------------------------------------------------------------
// Tiled 160x160 transpose, M independent matrices.
// mode 0: src_x -> g_xT (M = 8*128)
// mode 1: g_feat[dirs 2,3] -> g_tmp (M = 2*8*128)
// ---------------------------------------------------------------------------
__global__ void transpose_kernel(const float* __restrict__ src_x, int mode) {
    __shared__ float t[32][33];
    int m  = blockIdx.x / 25;
    int tl = blockIdx.x % 25;
    int r0 = (tl / 5) * 32, c0 = (tl % 5) * 32;
    const float* s;
    float* d;
    if (mode == 0) { s = src_x  + (size_t)m * SPAT;              d = g_xT  + (size_t)m * SPAT; }
    else           { s = g_feat + (size_t)(16*128 + m) * SPAT;   d = g_tmp + (size_t)m * SPAT; }
    int x = threadIdx.x;
    for (int y = threadIdx.y; y < 32; y += 8)
        t[y][x] = s[(r0 + y) * 160 + c0 + x];
    __syncthreads();
    for (int y = threadIdx.y; y < 32; y += 8)
        d[(c0 + y) * 160 + r0 + x] = t[x][y];
}

// ---------------------------------------------------------------------------
// Pre kernel: out[line][p] = bias + sum_{c,d} in[c][line][p-1+d]*K
// dir0 selects the half: {0,1} read x (line=h, p=w); {2,3} read g_xT.
// Block: 256 threads = 128 o-channels x 2 position-halves (16 positions each).
// Weight loads software-pipelined one cp ahead. Same summation order as R9.
// ---------------------------------------------------------------------------
__global__ void __launch_bounds__(256) pre_kernel(const float* __restrict__ x,
                                                  const float* __restrict__ biases,
                                                  int dir0) {
    int bx   = blockIdx.x;          // 12800 = 2*8*160*5
    int tile = bx % 5;
    int line = (bx / 5) % 160;
    int b    = (bx / 800) % 8;
    int dir  = dir0 + bx / 6400;
    int t    = threadIdx.x;
    int o    = t & 127;
    int half = t >> 7;
    int p0   = tile * 32;
    int jb   = half * 16;           // this thread's first position (within tile)

    const float* src = ((dir < 2) ? x : g_xT) + (size_t)(b * 128) * SPAT;
    __shared__ float sb[34 * 18];   // [p(34)][c(16)], stride 18 (8B-aligned pairs)

    float2 acc[16];
#pragma unroll
    for (int j = 0; j < 16; ++j) acc[j] = make_float2(0.f, 0.f);

    const float2* wbase = g_wkp + dir * 24576;

    // staging mapping: c = t>>4 (16 channels), lane = t&15 covers positions
    int sc = t >> 4, lane = t & 15;

    for (int c0 = 0; c0 < 128; c0 += 16) {
        const float* srow = src + (size_t)(c0 + sc) * SPAT + line * 160;
#pragma unroll
        for (int pp = lane; pp < 34; pp += 16) {
            int pos = p0 - 1 + pp;
            float v = 0.f;
            if (pos >= 0 && pos < 160) v = srow[pos];
            sb[pp * 18 + sc] = v;
        }
        __syncthreads();

        const float2* wgrp = wbase + (c0 >> 1) * 384 + o;
        float2 k0 = wgrp[0], k1 = wgrp[128], k2 = wgrp[256];
        for (int cp = 0; cp < 8; ++cp) {
            int ncp = (cp < 7) ? cp + 1 : 7;
            const float2* wn = wgrp + ncp * 384;
            float2 n0 = wn[0], n1 = wn[128], n2 = wn[256];

            float2 v0 = *reinterpret_cast<const float2*>(sb + (jb + 0) * 18 + 2 * cp);
            float2 v1 = *reinterpret_cast<const float2*>(sb + (jb + 1) * 18 + 2 * cp);
#pragma unroll
            for (int j = 0; j < 16; ++j) {
                float2 v2 = *reinterpret_cast<const float2*>(sb + (jb + j + 2) * 18 + 2 * cp);
                acc[j] = ffma2f(v0, k0, acc[j]);
                acc[j] = ffma2f(v1, k1, acc[j]);
                acc[j] = ffma2f(v2, k2, acc[j]);
                v0 = v1; v1 = v2;
            }
            k0 = n0; k1 = n1; k2 = n2;
        }
        __syncthreads();
    }

    float bias = biases[dir * 128 + o];
    float* op = g_pre + ((size_t)(dir * 8 + b) * 128 + o) * SPAT + line * 160 + p0 + jb;
#pragma unroll
    for (int j4 = 0; j4 < 16; j4 += 4) {
        float4 r;
        r.x = acc[j4    ].x + acc[j4    ].y + bias;
        r.y = acc[j4 + 1].x + acc[j4 + 1].y + bias;
        r.z = acc[j4 + 2].x + acc[j4 + 2].y + bias;
        r.w = acc[j4 + 3].x + acc[j4 + 3].y + bias;
        *reinterpret_cast<float4*>(op + j4) = r;
    }
}

// ---------------------------------------------------------------------------
// Fused 4-line recurrence step, 256 threads = 128 o x 2 j-halves.
// Each launch advances all 4 dirs, 8 batches by FOUR scan lines with halo
// recompute (line l computes 22-2l positions; each half does 11-l).
// prev line for l=0 staged COALESCED from g_feat; lines 1..3 from SMEM
// ping-pong (row stride 130 -> <=2-way bank conflicts on staging stores).
// Weight loads software-pipelined two cp ahead. Same summation order.
// Grid: 4 dirs * 8 b * 10 tiles = 320 blocks.
// ---------------------------------------------------------------------------
__global__ void __launch_bounds__(256) step4_kernel(const float* __restrict__ prelu_a,
                                                    int g) {
    int bx   = blockIdx.x;
    int tile = bx % 10;
    int b    = (bx / 10) % 8;
    int dir  = bx / 80;
    int t    = threadIdx.x;
    int o    = t & 127;
    int half = t >> 7;
    int p0   = tile * 16;
    int base = p0 - 4;                     // buffer row r <-> global pos base+r

    bool fwd = (dir == 0) || (dir == 2);
    const float* pb = g_pre  + (size_t)(dir * 8 + b) * 128 * SPAT;
    float*       yb = g_feat + (size_t)(dir * 8 + b) * 128 * SPAT;

    __shared__ float buf0[24 * 130];
    __shared__ float buf1[24 * 130];
    float* sprev = buf0;
    float* scur  = buf1;

    int s0 = 4 * g;
    // stage y of line (s0-1) coalesced: thread = position, loop channels
    {
        int sp = s0 - 1;
        int Lp = fwd ? sp : 159 - sp;
        const float* src = yb + (size_t)(Lp < 0 ? 0 : Lp) * 160;
        int r  = t & 31;
        int cb = t >> 5;                   // 8 channels per pass
        if (r < 24) {
            int gp = base + r;
            bool ok = (g > 0 && gp >= 0 && gp < 160);
#pragma unroll
            for (int c = cb; c < 128; c += 8) {
                float v = ok ? src[(size_t)c * SPAT + gp] : 0.f;
                sprev[r * 130 + c] = v;
            }
        }
    }
    __syncthreads();

    float s  = g_s [dir * 128 + o];
    float sh = g_sh[dir * 128 + o];
    float a  = prelu_a[dir];
    const float2* wbase = g_wkp + dir * 24576;

#pragma unroll
    for (int l = 0; l < 4; ++l) {
        int sidx = s0 + l;
        int L  = fwd ? sidx : 159 - sidx;
        const int nh = 11 - l;             // positions per half this line
        int jofs = half * nh;              // this thread's first j
        int q0 = p0 - (3 - l);             // global pos of j=0

        float2 acc[11];
#pragma unroll
        for (int j = 0; j < nh; ++j) acc[j] = make_float2(0.f, 0.f);

        if (sidx > 0) {
            int row0 = l + jofs;
            // depth-2 weight pipeline
            const float2* wA = wbase + o;
            float2 a0 = wA[0], a1 = wA[128], a2 = wA[256];
            const float2* wB = wbase + 384 + o;
            float2 b0 = wB[0], b1 = wB[128], b2 = wB[256];
            for (int cp = 0; cp < 64; ++cp) {
                int nc = (cp + 2 < 64) ? cp + 2 : 63;
                const float2* wC = wbase + nc * 384 + o;
                float2 c0_ = wC[0], c1_ = wC[128], c2_ = wC[256];

                float2 v0 = *reinterpret_cast<const float2*>(sprev + (row0    ) * 130 + 2 * cp);
                float2 v1 = *reinterpret_cast<const float2*>(sprev + (row0 + 1) * 130 + 2 * cp);
#pragma unroll
                for (int j = 0; j < nh; ++j) {
                    float2 v2 = *reinterpret_cast<const float2*>(sprev + (row0 + j + 2) * 130 + 2 * cp);
                    acc[j] = ffma2f(v0, a0, acc[j]);
                    acc[j] = ffma2f(v1, a1, acc[j]);
                    acc[j] = ffma2f(v2, a2, acc[j]);
                    v0 = v1; v1 = v2;
                }
                a0 = b0; a1 = b1; a2 = b2;
                b0 = c0_; b1 = c1_; b2 = c2_;
            }
        }

        const float* prow = pb + (size_t)o * SPAT + (size_t)L * 160;
        float*       wrow = yb + (size_t)o * SPAT + (size_t)L * 160;
#pragma unroll
        for (int jj = 0; jj < nh; ++jj) {
            int j  = jofs + jj;
            int gp = q0 + j;
            float y = 0.f;
            if (gp >= 0 && gp < 160) {
                float h = prow[gp] + acc[jj].x + acc[jj].y;
                y = h * s + sh;
                y = (y >= 0.f) ? y : a * y;
            }
            scur[(1 + l + j) * 130 + o] = y;
            if (j >= 3 - l && j < 19 - l)   // owned window [p0, p0+16)
                wrow[gp] = y;
        }
        __syncthreads();
        float* t_ = sprev; sprev = scur; scur = t_;
    }
}

// ---------------------------------------------------------------------------
// Fusion: out[o] = relu( sum_q feat[q]*wf[q][o]*finv + fc[o] ), q = dir*128+c.
// dirs 0,1 from g_feat (canonical), dirs 2,3 from g_tmp (transposed back).
// Weight loads software-pipelined one cp ahead.
// ---------------------------------------------------------------------------
__global__ void __launch_bounds__(128) fus_kernel(float* __restrict__ out) {
    int bx   = blockIdx.x;          // 12800 = 8*160*10
    int tile = bx % 10;
    int hh   = (bx / 10) % 160;
    int b    = bx / 1600;
    int t  = threadIdx.x;
    int ol = t & 63;
    int wg = t >> 6;
    int w0 = tile * 16;

    __shared__ float fs[16 * 16];   // [j][c]
    float2 acc0[8], acc1[8];
#pragma unroll
    for (int j = 0; j < 8; ++j) { acc0[j] = make_float2(0.f, 0.f); acc1[j] = make_float2(0.f, 0.f); }

    for (int q0 = 0; q0 < 512; q0 += 16) {
        for (int i = t; i < 256; i += 128) {
            int c = i >> 4, j = i & 15;
            int q = q0 + c; int dir = q >> 7; int cc = q & 127;
            const float* fp = (dir < 2)
                ? (g_feat + ((size_t)(dir * 8 + b) * 128 + cc) * SPAT)
                : (g_tmp  + ((size_t)((dir - 2) * 8 + b) * 128 + cc) * SPAT);
            fs[j * 16 + c] = fp[hh * 160 + w0 + j];
        }
        __syncthreads();

        int qb = q0 >> 1;
        float2 wa = g_wfp[qb * 128 + ol];
        float2 wb = g_wfp[qb * 128 + ol + 64];
        for (int cp = 0; cp < 8; ++cp) {
            int nqp = qb + ((cp < 7) ? cp + 1 : 7);
            float2 na = g_wfp[nqp * 128 + ol];
            float2 nb = g_wfp[nqp * 128 + ol + 64];
#pragma unroll
            for (int jj = 0; jj < 8; ++jj) {
                float2 v = *reinterpret_cast<const float2*>(fs + (wg * 8 + jj) * 16 + 2 * cp);
                acc0[jj] = ffma2f(v, wa, acc0[jj]);
                acc1[jj] = ffma2f(v, wb, acc1[jj]);
            }
            wa = na; wb = nb;
        }
        __syncthreads();
    }

    float c0v = g_fc[ol], c1v = g_fc[ol + 64];
    float* ob0 = out + (((size_t)b * 128 + ol     ) * 160 + hh) * 160 + w0 + wg * 8;
    float* ob1 = out + (((size_t)b * 128 + ol + 64) * 160 + hh) * 160 + w0 + wg * 8;
#pragma unroll
    for (int j4 = 0; j4 < 8; j4 += 4) {
        float4 r;
        r.x = fmaxf(acc0[j4    ].x + acc0[j4    ].y + c0v, 0.f);
        r.y = fmaxf(acc0[j4 + 1].x + acc0[j4 + 1].y + c0v, 0.f);
        r.z = fmaxf(acc0[j4 + 2].x + acc0[j4 + 2].y + c0v, 0.f);
        r.w = fmaxf(acc0[j4 + 3].x + acc0[j4 + 3].y + c0v, 0.f);
        *reinterpret_cast<float4*>(ob0 + j4) = r;
        float4 q;
        q.x = fmaxf(acc1[j4    ].x + acc1[j4    ].y + c1v, 0.f);
        q.y = fmaxf(acc1[j4 + 1].x + acc1[j4 + 1].y + c1v, 0.f);
        q.z = fmaxf(acc1[j4 + 2].x + acc1[j4 + 2].y + c1v, 0.f);
        q.w = fmaxf(acc1[j4 + 3].x + acc1[j4 + 3].y + c1v, 0.f);
        *reinterpret_cast<float4*>(ob1 + j4) = q;
    }
}

// ---------------------------------------------------------------------------
extern "C" void kernel_launch(void* const* d_in, const int* in_sizes, int n_in,
                              void* d_out, int out_size) {
    const float* x         = (const float*)d_in[0];
    const float* kernels   = (const float*)d_in[1];
    const float* biases    = (const float*)d_in[2];
    const float* bn_gamma  = (const float*)d_in[3];
    const float* bn_beta   = (const float*)d_in[4];
    const float* bn_mean   = (const float*)d_in[5];
    const float* bn_var    = (const float*)d_in[6];
    const float* prelu_a   = (const float*)d_in[7];
    const float* fus_w     = (const float*)d_in[8];
    const float* fus_b     = (const float*)d_in[9];
    const float* fbn_gamma = (const float*)d_in[10];
    const float* fbn_beta  = (const float*)d_in[11];
    const float* fbn_mean  = (const float*)d_in[12];
    const float* fbn_var   = (const float*)d_in[13];

    prep_kernel<<<128, 256>>>(kernels, bn_gamma, bn_beta, bn_mean, bn_var,
                              fus_w, fus_b, fbn_gamma, fbn_beta, fbn_mean, fbn_var);

    // x -> xT so column directions scan along a contiguous axis
    transpose_kernel<<<8 * 128 * 25, dim3(32, 8)>>>(x, 0);

    // one pad launch: with harness prefix 0/1/2, ncu -s 5 -c 1 captures
    // step4(g=0) / pre(dirs2-3) / pre(dirs0-1) respectively — all real kernels
    noop_kernel<<<1, 32>>>();

    // pre-activations, two halves (dirs 0-1, dirs 2-3)
    pre_kernel<<<12800, 256>>>(x, biases, 0);
    pre_kernel<<<12800, 256>>>(x, biases, 2);

    // 40 fused recurrence launches; each advances all dirs/batches by 4 lines
    for (int g = 0; g < 40; ++g)
        step4_kernel<<<320, 256>>>(prelu_a, g);

    // bring dirs 2,3 back to canonical [h][w] layout for fusion
    transpose_kernel<<<2 * 8 * 128 * 25, dim3(32, 8)>>>(x, 1);

    // fused 1x1 conv + BN + ReLU
    fus_kernel<<<12800, 128>>>((float*)d_out);
}

// round 12
// speedup vs baseline: 1.0131x; 1.0131x over previous
#include <cuda_runtime.h>
#include <cuda_bf16.h>
#include <cstdint>

// ---------------------------------------------------------------------------
// SpatialConvModule (SCNN-style): 4 directional recurrent 3-tap convs + fusion
// B=8, C=128, H=W=160. All fp32, packed f32x2 FMA (sm_103a).
// R12: LDS.128 dual-channel-pair inner loops (6 FFMA2 per smem load),
//      step tile 16->8 (640 blocks), pre single-launch so ncu captures step4.
// ---------------------------------------------------------------------------

#define EPSV 1e-5f
#define SPAT 25600            // 160*160

// ---- static device scratch (allocation-free rule) -------------------------
__device__ float  g_pre [4ull*8*128*160*160];  // pre-activations (read-only in steps)
__device__ float  g_feat[4ull*8*128*160*160];  // recurrence outputs (features)
__device__ float  g_xT [8ull*128*160*160];     // x transposed per (b,c): [w][h]
__device__ float  g_tmp[2ull*8*128*160*160];   // dirs 2,3 feat transposed back
__device__ float2 g_wkp[4*64*3*128];           // [dir][cpair][tap][o] (even,odd c)
__device__ float2 g_wfp[256*128];              // [qpair][o], pre-scaled by fbn inv
__device__ float  g_s[512], g_sh[512], g_fc[128];

// packed fp32x2 fma: d = a*b + c (elementwise on both halves)
__device__ __forceinline__ float2 ffma2f(float2 a, float2 b, float2 c) {
    float2 d;
    asm("fma.rn.f32x2 %0, %1, %2, %3;"
        : "=l"(reinterpret_cast<unsigned long long&>(d))
        : "l"(reinterpret_cast<unsigned long long&>(a)),
          "l"(reinterpret_cast<unsigned long long&>(b)),
          "l"(reinterpret_cast<unsigned long long&>(c)));
    return d;
}
__device__ __forceinline__ float2 lo2(const float4& v) { return make_float2(v.x, v.y); }
__device__ __forceinline__ float2 hi2(const float4& v) { return make_float2(v.z, v.w); }

// ---------------------------------------------------------------------------
// Prep: repack conv weights to [dir][cpair][tap][o] float2, fold BN into
// scale/shift, pre-scale fusion weights by fused-BN inv.
// ---------------------------------------------------------------------------
__global__ void prep_kernel(const float* __restrict__ kern,
                            const float* __restrict__ bg, const float* __restrict__ bb,
                            const float* __restrict__ bm, const float* __restrict__ bv,
                            const float* __restrict__ fw, const float* __restrict__ fb,
                            const float* __restrict__ fg, const float* __restrict__ fbeta,
                            const float* __restrict__ fm, const float* __restrict__ fv) {
    const int NWK = 98304, NWF = 32768;
    int total = NWK + NWF + 512 + 128;
    for (int i = blockIdx.x * blockDim.x + threadIdx.x; i < total;
         i += gridDim.x * blockDim.x) {
        if (i < NWK) {
            int dir = i / 24576; int r = i % 24576;
            int cp = r / 384;    int r2 = r % 384;
            int d = r2 / 128;    int o = r2 % 128;
            int c0 = 2 * cp;
            float a0, a1;
            if (dir < 2) {  // 1x3 kernel: kh=1, kw=d
                a0 = kern[(((dir*128 + o)*128 + c0    )*3 + 1)*3 + d];
                a1 = kern[(((dir*128 + o)*128 + c0 + 1)*3 + 1)*3 + d];
            } else {        // 3x1 kernel: kh=d, kw=1
                a0 = kern[(((dir*128 + o)*128 + c0    )*3 + d)*3 + 1];
                a1 = kern[(((dir*128 + o)*128 + c0 + 1)*3 + d)*3 + 1];
            }
            g_wkp[i] = make_float2(a0, a1);
        } else if (i < NWK + NWF) {
            int idx = i - NWK; int qp = idx / 128; int o = idx % 128;
            float fs = fg[o] * rsqrtf(fv[o] + EPSV);
            g_wfp[idx] = make_float2(fw[o*512 + 2*qp] * fs, fw[o*512 + 2*qp + 1] * fs);
        } else if (i < NWK + NWF + 512) {
            int idx = i - NWK - NWF;
            float s = bg[idx] * rsqrtf(bv[idx] + EPSV);
            g_s[idx] = s; g_sh[idx] = bb[idx] - bm[idx] * s;
        } else {
            int o = i - NWK - NWF - 512;
            float fs = fg[o] * rsqrtf(fv[o] + EPSV);
            g_fc[o] = fb[o] * fs + fbeta[o] - fm[o] * fs;
        }
    }
}

// ---------------------------------------------------------------------------
// Tiled 160x160 transpose, M independent matrices.
// mode 0: src_x -> g_xT (M = 8*128)
// mode 1: g_feat[dirs 2,3] -> g_tmp (M = 2*8*128)
// ---------------------------------------------------------------------------
__global__ void transpose_kernel(const float* __restrict__ src_x, int mode) {
    __shared__ float t[32][33];
    int m  = blockIdx.x / 25;
    int tl = blockIdx.x % 25;
    int r0 = (tl / 5) * 32, c0 = (tl % 5) * 32;
    const float* s;
    float* d;
    if (mode == 0) { s = src_x  + (size_t)m * SPAT;              d = g_xT  + (size_t)m * SPAT; }
    else           { s = g_feat + (size_t)(16*128 + m) * SPAT;   d = g_tmp + (size_t)m * SPAT; }
    int x = threadIdx.x;
    for (int y = threadIdx.y; y < 32; y += 8)
        t[y][x] = s[(r0 + y) * 160 + c0 + x];
    __syncthreads();
    for (int y = threadIdx.y; y < 32; y += 8)
        d[(c0 + y) * 160 + r0 + x] = t[x][y];
}

// ---------------------------------------------------------------------------
// Pre kernel: out[line][p] = bias + sum_{c,d} in[c][line][p-1+d]*K
// dirs {0,1} read x (line=h, p=w); {2,3} read g_xT.
// Block: 256 threads = 128 o-channels x 2 position-halves (16 positions each).
// Inner loop: LDS.128 (4 channels, 1 position) -> 6 FFMA2; value prefetch VN;
// weight prefetch one cp2 (2 channel-pairs) ahead.
// ---------------------------------------------------------------------------
__global__ void __launch_bounds__(256) pre_kernel(const float* __restrict__ x,
                                                  const float* __restrict__ biases) {
    int bx   = blockIdx.x;          // 25600 = 4*8*160*5
    int tile = bx % 5;
    int line = (bx / 5) % 160;
    int b    = (bx / 800) % 8;
    int dir  = bx / 6400;
    int t    = threadIdx.x;
    int o    = t & 127;
    int half = t >> 7;
    int p0   = tile * 32;
    int jb   = half * 16;           // this thread's first position (within tile)

    const float* src = ((dir < 2) ? x : g_xT) + (size_t)(b * 128) * SPAT;
    __shared__ __align__(16) float sb[35 * 20];  // [p(34 used)][c(16)], stride 20

    float2 acc[16];
#pragma unroll
    for (int j = 0; j < 16; ++j) acc[j] = make_float2(0.f, 0.f);

    const float2* wbase = g_wkp + dir * 24576;
    int sc = t >> 4, lane = t & 15;

    for (int c0 = 0; c0 < 128; c0 += 16) {
        const float* srow = src + (size_t)(c0 + sc) * SPAT + line * 160;
#pragma unroll
        for (int pp = lane; pp < 34; pp += 16) {
            int pos = p0 - 1 + pp;
            float v = 0.f;
            if (pos >= 0 && pos < 160) v = srow[pos];
            sb[pp * 20 + sc] = v;
        }
        __syncthreads();

        const float2* wp = wbase + (c0 >> 1) * 384 + o;
        float2 k0a = wp[0],  k1a = wp[128], k2a = wp[256];
        float2 k0b = wp[384], k1b = wp[512], k2b = wp[640];
#pragma unroll
        for (int cp2 = 0; cp2 < 4; ++cp2) {
            const float2* wn = wp + ((cp2 < 3) ? 768 : 0);
            float2 n0a = wn[0],  n1a = wn[128], n2a = wn[256];
            float2 n0b = wn[384], n1b = wn[512], n2b = wn[640];

            const float* col = sb + 4 * cp2;
            float4 V0 = *reinterpret_cast<const float4*>(col + (jb + 0) * 20);
            float4 V1 = *reinterpret_cast<const float4*>(col + (jb + 1) * 20);
            float4 V2 = *reinterpret_cast<const float4*>(col + (jb + 2) * 20);
#pragma unroll
            for (int j = 0; j < 16; ++j) {
                float4 VN = *reinterpret_cast<const float4*>(col + (jb + j + 3) * 20);
                acc[j] = ffma2f(lo2(V0), k0a, acc[j]);
                acc[j] = ffma2f(hi2(V0), k0b, acc[j]);
                acc[j] = ffma2f(lo2(V1), k1a, acc[j]);
                acc[j] = ffma2f(hi2(V1), k1b, acc[j]);
                acc[j] = ffma2f(lo2(V2), k2a, acc[j]);
                acc[j] = ffma2f(hi2(V2), k2b, acc[j]);
                V0 = V1; V1 = V2; V2 = VN;
            }
            k0a = n0a; k1a = n1a; k2a = n2a;
            k0b = n0b; k1b = n1b; k2b = n2b;
            wp = wn;
        }
        __syncthreads();
    }

    float bias = biases[dir * 128 + o];
    float* op = g_pre + ((size_t)(dir * 8 + b) * 128 + o) * SPAT + line * 160 + p0 + jb;
#pragma unroll
    for (int j4 = 0; j4 < 16; j4 += 4) {
        float4 r;
        r.x = acc[j4    ].x + acc[j4    ].y + bias;
        r.y = acc[j4 + 1].x + acc[j4 + 1].y + bias;
        r.z = acc[j4 + 2].x + acc[j4 + 2].y + bias;
        r.w = acc[j4 + 3].x + acc[j4 + 3].y + bias;
        *reinterpret_cast<float4*>(op + j4) = r;
    }
}

// ---------------------------------------------------------------------------
// Fused 4-line recurrence step, tile width 8, 256 threads = 128 o x 2 j-halves.
// Each launch advances all 4 dirs, 8 batches by FOUR scan lines with halo
// recompute (line l computes 14-2l positions; each half does 7-l).
// prev line for l=0 staged coalesced from g_feat; lines 1..3 from SMEM
// ping-pong (rows 17, stride 132 floats = 16B-aligned for LDS.128).
// Inner loop: LDS.128 -> 6 FFMA2, weights prefetched one cp2 ahead.
// Grid: 4 dirs * 8 b * 20 tiles = 640 blocks.
// ---------------------------------------------------------------------------
__global__ void __launch_bounds__(256) step4_kernel(const float* __restrict__ prelu_a,
                                                    int g) {
    int bx   = blockIdx.x;
    int tile = bx % 20;
    int b    = (bx / 20) % 8;
    int dir  = bx / 160;
    int t    = threadIdx.x;
    int o    = t & 127;
    int half = t >> 7;
    int p0   = tile * 8;
    int base = p0 - 4;                     // buffer row r <-> global pos base+r

    bool fwd = (dir == 0) || (dir == 2);
    const float* pb = g_pre  + (size_t)(dir * 8 + b) * 128 * SPAT;
    float*       yb = g_feat + (size_t)(dir * 8 + b) * 128 * SPAT;

    __shared__ __align__(16) float buf0[17 * 132];
    __shared__ __align__(16) float buf1[17 * 132];
    float* sprev = buf0;
    float* scur  = buf1;

    int s0 = 4 * g;
    // stage y of line (s0-1) coalesced: thread = position (16 rows), loop channels
    {
        int sp = s0 - 1;
        int Lp = fwd ? sp : 159 - sp;
        const float* src = yb + (size_t)(Lp < 0 ? 0 : Lp) * 160;
        int r  = t & 15;
        int cb = t >> 4;                   // 16 channel-groups of 8
        int gp = base + r;
        bool ok = (g > 0 && gp >= 0 && gp < 160);
#pragma unroll
        for (int c = cb; c < 128; c += 16) {
            float v = ok ? src[(size_t)c * SPAT + gp] : 0.f;
            sprev[r * 132 + c] = v;
        }
    }
    __syncthreads();

    float s  = g_s [dir * 128 + o];
    float sh = g_sh[dir * 128 + o];
    float a  = prelu_a[dir];
    const float2* wbase = g_wkp + dir * 24576;

#pragma unroll
    for (int l = 0; l < 4; ++l) {
        int sidx = s0 + l;
        int L  = fwd ? sidx : 159 - sidx;
        const int nh = 7 - l;              // positions per half this line
        int jofs = half * nh;              // this thread's first j
        int q0 = p0 - (3 - l);             // global pos of j=0

        float2 acc[7];
#pragma unroll
        for (int j = 0; j < nh; ++j) acc[j] = make_float2(0.f, 0.f);

        if (sidx > 0) {
            int row0 = l + jofs;
            const float2* wp = wbase + o;
            float2 k0a = wp[0],  k1a = wp[128], k2a = wp[256];
            float2 k0b = wp[384], k1b = wp[512], k2b = wp[640];
            for (int cp2 = 0; cp2 < 32; ++cp2) {
                const float2* wn = wbase + ((cp2 < 31) ? (cp2 + 1) : cp2) * 768 + o;
                float2 n0a = wn[0],  n1a = wn[128], n2a = wn[256];
                float2 n0b = wn[384], n1b = wn[512], n2b = wn[640];

                const float* col = sprev + 4 * cp2;
                float4 V0 = *reinterpret_cast<const float4*>(col + (row0    ) * 132);
                float4 V1 = *reinterpret_cast<const float4*>(col + (row0 + 1) * 132);
                float4 V2 = *reinterpret_cast<const float4*>(col + (row0 + 2) * 132);
#pragma unroll
                for (int j = 0; j < nh; ++j) {
                    float4 VN = *reinterpret_cast<const float4*>(col + (row0 + j + 3) * 132);
                    acc[j] = ffma2f(lo2(V0), k0a, acc[j]);
                    acc[j] = ffma2f(hi2(V0), k0b, acc[j]);
                    acc[j] = ffma2f(lo2(V1), k1a, acc[j]);
                    acc[j] = ffma2f(hi2(V1), k1b, acc[j]);
                    acc[j] = ffma2f(lo2(V2), k2a, acc[j]);
                    acc[j] = ffma2f(hi2(V2), k2b, acc[j]);
                    V0 = V1; V1 = V2; V2 = VN;
                }
                k0a = n0a; k1a = n1a; k2a = n2a;
                k0b = n0b; k1b = n1b; k2b = n2b;
            }
        }

        const float* prow = pb + (size_t)o * SPAT + (size_t)L * 160;
        float*       wrow = yb + (size_t)o * SPAT + (size_t)L * 160;
#pragma unroll
        for (int jj = 0; jj < nh; ++jj) {
            int j  = jofs + jj;
            int gp = q0 + j;
            float y = 0.f;
            if (gp >= 0 && gp < 160) {
                float h = prow[gp] + acc[jj].x + acc[jj].y;
                y = h * s + sh;
                y = (y >= 0.f) ? y : a * y;
            }
            scur[(1 + l + j) * 132 + o] = y;
            if (j >= 3 - l && j < 11 - l)   // owned window [p0, p0+8)
                wrow[gp] = y;
        }
        __syncthreads();
        float* t_ = sprev; sprev = scur; scur = t_;
    }
}

// ---------------------------------------------------------------------------
// Fusion: out[o] = relu( sum_q feat[q]*wf[q][o]*finv + fc[o] ), q = dir*128+c.
// dirs 0,1 from g_feat (canonical), dirs 2,3 from g_tmp (transposed back).
// Inner loop: LDS.128 (4 q-channels) -> 4 FFMA2.
// ---------------------------------------------------------------------------
__global__ void __launch_bounds__(128) fus_kernel(float* __restrict__ out) {
    int bx   = blockIdx.x;          // 12800 = 8*160*10
    int tile = bx % 10;
    int hh   = (bx / 10) % 160;
    int b    = bx / 1600;
    int t  = threadIdx.x;
    int ol = t & 63;
    int wg = t >> 6;
    int w0 = tile * 16;

    __shared__ __align__(16) float fs[16 * 16];   // [j][c]
    float2 acc0[8], acc1[8];
#pragma unroll
    for (int j = 0; j < 8; ++j) { acc0[j] = make_float2(0.f, 0.f); acc1[j] = make_float2(0.f, 0.f); }

    for (int q0 = 0; q0 < 512; q0 += 16) {
        for (int i = t; i < 256; i += 128) {
            int c = i >> 4, j = i & 15;
            int q = q0 + c; int dir = q >> 7; int cc = q & 127;
            const float* fp = (dir < 2)
                ? (g_feat + ((size_t)(dir * 8 + b) * 128 + cc) * SPAT)
                : (g_tmp  + ((size_t)((dir - 2) * 8 + b) * 128 + cc) * SPAT);
            fs[j * 16 + c] = fp[hh * 160 + w0 + j];
        }
        __syncthreads();

        int qb = q0 >> 1;
#pragma unroll
        for (int cp2 = 0; cp2 < 4; ++cp2) {
            int qp = qb + 2 * cp2;
            float2 wa0 = g_wfp[qp * 128 + ol];
            float2 wb0 = g_wfp[qp * 128 + ol + 64];
            float2 wa1 = g_wfp[(qp + 1) * 128 + ol];
            float2 wb1 = g_wfp[(qp + 1) * 128 + ol + 64];
#pragma unroll
            for (int jj = 0; jj < 8; ++jj) {
                float4 V = *reinterpret_cast<const float4*>(fs + (wg * 8 + jj) * 16 + 4 * cp2);
                acc0[jj] = ffma2f(lo2(V), wa0, acc0[jj]);
                acc0[jj] = ffma2f(hi2(V), wa1, acc0[jj]);
                acc1[jj] = ffma2f(lo2(V), wb0, acc1[jj]);
                acc1[jj] = ffma2f(hi2(V), wb1, acc1[jj]);
            }
        }
        __syncthreads();
    }

    float c0v = g_fc[ol], c1v = g_fc[ol + 64];
    float* ob0 = out + (((size_t)b * 128 + ol     ) * 160 + hh) * 160 + w0 + wg * 8;
    float* ob1 = out + (((size_t)b * 128 + ol + 64) * 160 + hh) * 160 + w0 + wg * 8;
#pragma unroll
    for (int j4 = 0; j4 < 8; j4 += 4) {
        float4 r;
        r.x = fmaxf(acc0[j4    ].x + acc0[j4    ].y + c0v, 0.f);
        r.y = fmaxf(acc0[j4 + 1].x + acc0[j4 + 1].y + c0v, 0.f);
        r.z = fmaxf(acc0[j4 + 2].x + acc0[j4 + 2].y + c0v, 0.f);
        r.w = fmaxf(acc0[j4 + 3].x + acc0[j4 + 3].y + c0v, 0.f);
        *reinterpret_cast<float4*>(ob0 + j4) = r;
        float4 q;
        q.x = fmaxf(acc1[j4    ].x + acc1[j4    ].y + c1v, 0.f);
        q.y = fmaxf(acc1[j4 + 1].x + acc1[j4 + 1].y + c1v, 0.f);
        q.z = fmaxf(acc1[j4 + 2].x + acc1[j4 + 2].y + c1v, 0.f);
        q.w = fmaxf(acc1[j4 + 3].x + acc1[j4 + 3].y + c1v, 0.f);
        *reinterpret_cast<float4*>(ob1 + j4) = q;
    }
}

// ---------------------------------------------------------------------------
extern "C" void kernel_launch(void* const* d_in, const int* in_sizes, int n_in,
                              void* d_out, int out_size) {
    const float* x         = (const float*)d_in[0];
    const float* kernels   = (const float*)d_in[1];
    const float* biases    = (const float*)d_in[2];
    const float* bn_gamma  = (const float*)d_in[3];
    const float* bn_beta   = (const float*)d_in[4];
    const float* bn_mean   = (const float*)d_in[5];
    const float* bn_var    = (const float*)d_in[6];
    const float* prelu_a   = (const float*)d_in[7];
    const float* fus_w     = (const float*)d_in[8];
    const float* fus_b     = (const float*)d_in[9];
    const float* fbn_gamma = (const float*)d_in[10];
    const float* fbn_beta  = (const float*)d_in[11];
    const float* fbn_mean  = (const float*)d_in[12];
    const float* fbn_var   = (const float*)d_in[13];

    // our idx 0..2; harness prefix = 2 -> ncu -s 5 captures our idx 3 = step4(g=0)
    prep_kernel<<<128, 256>>>(kernels, bn_gamma, bn_beta, bn_mean, bn_var,
                              fus_w, fus_b, fbn_gamma, fbn_beta, fbn_mean, fbn_var);

    transpose_kernel<<<8 * 128 * 25, dim3(32, 8)>>>(x, 0);

    pre_kernel<<<25600, 256>>>(x, biases);

    // 40 fused recurrence launches; each advances all dirs/batches by 4 lines
    for (int g = 0; g < 40; ++g)
        step4_kernel<<<640, 256>>>(prelu_a, g);

    // bring dirs 2,3 back to canonical [h][w] layout for fusion
    transpose_kernel<<<2 * 8 * 128 * 25, dim3(32, 8)>>>(x, 1);

    // fused 1x1 conv + BN + ReLU
    fus_kernel<<<12800, 128>>>((float*)d_out);
}

// round 13
// speedup vs baseline: 1.2565x; 1.2402x over previous
#include <cuda_runtime.h>
#include <cuda_bf16.h>
#include <cstdint>

// ---------------------------------------------------------------------------
// SpatialConvModule (SCNN-style): 4 directional recurrent 3-tap convs + fusion
// B=8, C=128, H=W=160. All fp32, packed f32x2 FMA (sm_103a).
// R13: step4 rebuilt — 128 thr/block full-width tiles (np=14-2l), float4
//      weight table (3 LDG.128/cp2), smem-staged pre + coalesced y writer.
// ---------------------------------------------------------------------------

#define EPSV 1e-5f
#define SPAT 25600            // 160*160

// ---- static device scratch (allocation-free rule) -------------------------
__device__ float  g_pre [4ull*8*128*160*160];  // pre-activations (read-only in steps)
__device__ float  g_feat[4ull*8*128*160*160];  // recurrence outputs (features)
__device__ float  g_xT [8ull*128*160*160];     // x transposed per (b,c): [w][h]
__device__ float  g_tmp[2ull*8*128*160*160];   // dirs 2,3 feat transposed back
__device__ float4 g_wk4[4*32*3*128];           // [dir][cp2][tap][o]: channels 4cp2..4cp2+3
__device__ float2 g_wfp[256*128];              // [qpair][o], pre-scaled by fbn inv
__device__ float  g_s[512], g_sh[512], g_fc[128];

// packed fp32x2 fma: d = a*b + c (elementwise on both halves)
__device__ __forceinline__ float2 ffma2f(float2 a, float2 b, float2 c) {
    float2 d;
    asm("fma.rn.f32x2 %0, %1, %2, %3;"
        : "=l"(reinterpret_cast<unsigned long long&>(d))
        : "l"(reinterpret_cast<unsigned long long&>(a)),
          "l"(reinterpret_cast<unsigned long long&>(b)),
          "l"(reinterpret_cast<unsigned long long&>(c)));
    return d;
}
__device__ __forceinline__ float2 lo2(const float4& v) { return make_float2(v.x, v.y); }
__device__ __forceinline__ float2 hi2(const float4& v) { return make_float2(v.z, v.w); }

// ---------------------------------------------------------------------------
// Prep: build float4 conv-weight table [dir][cp2][tap][o] (channels 4cp2..+3),
// fold BN into scale/shift, pre-scale fusion weights by fused-BN inv.
// ---------------------------------------------------------------------------
__global__ void prep_kernel(const float* __restrict__ kern,
                            const float* __restrict__ bg, const float* __restrict__ bb,
                            const float* __restrict__ bm, const float* __restrict__ bv,
                            const float* __restrict__ fw, const float* __restrict__ fb,
                            const float* __restrict__ fg, const float* __restrict__ fbeta,
                            const float* __restrict__ fm, const float* __restrict__ fv) {
    const int NW4 = 49152, NWF = 32768;   // 4*32*3*128, 256*128
    int total = NW4 + NWF + 512 + 128;
    for (int i = blockIdx.x * blockDim.x + threadIdx.x; i < total;
         i += gridDim.x * blockDim.x) {
        if (i < NW4) {
            int dir = i / 12288; int r = i % 12288;
            int cp2 = r / 384;   int r2 = r % 384;
            int tap = r2 / 128;  int o = r2 % 128;
            int c0 = 4 * cp2;
            float w[4];
#pragma unroll
            for (int q = 0; q < 4; ++q) {
                int c = c0 + q;
                if (dir < 2)   // 1x3 kernel: kh=1, kw=tap
                    w[q] = kern[(((dir*128 + o)*128 + c)*3 + 1)*3 + tap];
                else           // 3x1 kernel: kh=tap, kw=1
                    w[q] = kern[(((dir*128 + o)*128 + c)*3 + tap)*3 + 1];
            }
            g_wk4[i] = make_float4(w[0], w[1], w[2], w[3]);
        } else if (i < NW4 + NWF) {
            int idx = i - NW4; int qp = idx / 128; int o = idx % 128;
            float fs = fg[o] * rsqrtf(fv[o] + EPSV);
            g_wfp[idx] = make_float2(fw[o*512 + 2*qp] * fs, fw[o*512 + 2*qp + 1] * fs);
        } else if (i < NW4 + NWF + 512) {
            int idx = i - NW4 - NWF;
            float s = bg[idx] * rsqrtf(bv[idx] + EPSV);
            g_s[idx] = s; g_sh[idx] = bb[idx] - bm[idx] * s;
        } else {
            int o = i - NW4 - NWF - 512;
            float fs = fg[o] * rsqrtf(fv[o] + EPSV);
            g_fc[o] = fb[o] * fs + fbeta[o] - fm[o] * fs;
        }
    }
}

// ---------------------------------------------------------------------------
// Tiled 160x160 transpose, M independent matrices.
// mode 0: src_x -> g_xT (M = 8*128)
// mode 1: g_feat[dirs 2,3] -> g_tmp (M = 2*8*128)
// ---------------------------------------------------------------------------
__global__ void transpose_kernel(const float* __restrict__ src_x, int mode) {
    __shared__ float t[32][33];
    int m  = blockIdx.x / 25;
    int tl = blockIdx.x % 25;
    int r0 = (tl / 5) * 32, c0 = (tl % 5) * 32;
    const float* s;
    float* d;
    if (mode == 0) { s = src_x  + (size_t)m * SPAT;              d = g_xT  + (size_t)m * SPAT; }
    else           { s = g_feat + (size_t)(16*128 + m) * SPAT;   d = g_tmp + (size_t)m * SPAT; }
    int x = threadIdx.x;
    for (int y = threadIdx.y; y < 32; y += 8)
        t[y][x] = s[(r0 + y) * 160 + c0 + x];
    __syncthreads();
    for (int y = threadIdx.y; y < 32; y += 8)
        d[(c0 + y) * 160 + r0 + x] = t[x][y];
}

// ---------------------------------------------------------------------------
// Pre kernel: out[line][p] = bias + sum_{c,d} in[c][line][p-1+d]*K
// dirs {0,1} read x (line=h, p=w); {2,3} read g_xT.
// Block: 256 threads = 128 o-channels x 2 position-halves (16 positions each).
// Inner loop: LDS.128 (4 channels) -> 6 FFMA2; weights float4, prefetch +1.
// ---------------------------------------------------------------------------
__global__ void __launch_bounds__(256) pre_kernel(const float* __restrict__ x,
                                                  const float* __restrict__ biases) {
    int bx   = blockIdx.x;          // 25600 = 4*8*160*5
    int tile = bx % 5;
    int line = (bx / 5) % 160;
    int b    = (bx / 800) % 8;
    int dir  = bx / 6400;
    int t    = threadIdx.x;
    int o    = t & 127;
    int half = t >> 7;
    int p0   = tile * 32;
    int jb   = half * 16;

    const float* src = ((dir < 2) ? x : g_xT) + (size_t)(b * 128) * SPAT;
    __shared__ __align__(16) float sb[35 * 20];  // [p(34 used)][c(16)], stride 20

    float2 acc[16];
#pragma unroll
    for (int j = 0; j < 16; ++j) acc[j] = make_float2(0.f, 0.f);

    const float4* wb4 = g_wk4 + dir * (32 * 3 * 128);
    int sc = t >> 4, lane = t & 15;

    float4 K0 = wb4[0 * 128 + o], K1 = wb4[1 * 128 + o], K2 = wb4[2 * 128 + o];
    int gcp2 = 0;
    for (int c0 = 0; c0 < 128; c0 += 16) {
        const float* srow = src + (size_t)(c0 + sc) * SPAT + line * 160;
#pragma unroll
        for (int pp = lane; pp < 34; pp += 16) {
            int pos = p0 - 1 + pp;
            float v = 0.f;
            if (pos >= 0 && pos < 160) v = srow[pos];
            sb[pp * 20 + sc] = v;
        }
        __syncthreads();

#pragma unroll
        for (int cp2l = 0; cp2l < 4; ++cp2l) {
            int ng = (gcp2 < 31) ? gcp2 + 1 : 31;
            float4 N0 = wb4[(ng * 3 + 0) * 128 + o];
            float4 N1 = wb4[(ng * 3 + 1) * 128 + o];
            float4 N2 = wb4[(ng * 3 + 2) * 128 + o];

            const float* col = sb + 4 * cp2l;
            float4 V0 = *reinterpret_cast<const float4*>(col + (jb + 0) * 20);
            float4 V1 = *reinterpret_cast<const float4*>(col + (jb + 1) * 20);
            float4 V2 = *reinterpret_cast<const float4*>(col + (jb + 2) * 20);
#pragma unroll
            for (int j = 0; j < 16; ++j) {
                float4 VN = *reinterpret_cast<const float4*>(col + (jb + j + 3) * 20);
                acc[j] = ffma2f(lo2(V0), lo2(K0), acc[j]);
                acc[j] = ffma2f(hi2(V0), hi2(K0), acc[j]);
                acc[j] = ffma2f(lo2(V1), lo2(K1), acc[j]);
                acc[j] = ffma2f(hi2(V1), hi2(K1), acc[j]);
                acc[j] = ffma2f(lo2(V2), lo2(K2), acc[j]);
                acc[j] = ffma2f(hi2(V2), hi2(K2), acc[j]);
                V0 = V1; V1 = V2; V2 = VN;
            }
            K0 = N0; K1 = N1; K2 = N2;
            ++gcp2;
        }
        __syncthreads();
    }

    float bias = biases[dir * 128 + o];
    float* op = g_pre + ((size_t)(dir * 8 + b) * 128 + o) * SPAT + line * 160 + p0 + jb;
#pragma unroll
    for (int j4 = 0; j4 < 16; j4 += 4) {
        float4 r;
        r.x = acc[j4    ].x + acc[j4    ].y + bias;
        r.y = acc[j4 + 1].x + acc[j4 + 1].y + bias;
        r.z = acc[j4 + 2].x + acc[j4 + 2].y + bias;
        r.w = acc[j4 + 3].x + acc[j4 + 3].y + bias;
        *reinterpret_cast<float4*>(op + j4) = r;
    }
}

// ---------------------------------------------------------------------------
// Fused 4-line recurrence step. 640 blocks x 128 threads (thread = o).
// Tile width 8; line l computes np = 14-2l positions per thread (halo
// recompute). Weights: 3 LDG.128 per cp2 (float4 table), prefetch +1.
// pre staged per line into SMEM (coalesced LDG); y written back via
// transposing coalesced writer. dir = bx&3 so co-resident blocks share
// one direction's weight set in L1.
// ---------------------------------------------------------------------------
__global__ void __launch_bounds__(128) step4_kernel(const float* __restrict__ prelu_a,
                                                    int g) {
    int bx   = blockIdx.x;
    int dir  = bx & 3;
    int b    = (bx >> 2) & 7;
    int tile = bx >> 5;                    // 0..19
    int o    = threadIdx.x;
    int t    = threadIdx.x;
    int p0   = tile * 8;
    int base = p0 - 4;                     // buffer row r <-> global pos base+r

    bool fwd = (dir == 0) || (dir == 2);
    const float* pb = g_pre  + (size_t)(dir * 8 + b) * 128 * SPAT;
    float*       yb = g_feat + (size_t)(dir * 8 + b) * 128 * SPAT;

    __shared__ __align__(16) float buf0[17 * 132];
    __shared__ __align__(16) float buf1[17 * 132];
    __shared__ __align__(16) float spre[16 * 132];
    float* sprev = buf0;
    float* scur  = buf1;

    int s0 = 4 * g;
    // stage y of line (s0-1): coalesced (lane = position, loop channels)
    {
        int sp = s0 - 1;
        int Lp = fwd ? sp : 159 - sp;
        const float* src = yb + (size_t)(Lp < 0 ? 0 : Lp) * 160;
        int r  = t & 15;
        int cb = t >> 4;                   // 8 channel-groups
        int gp = base + r;
        bool ok = (g > 0 && gp >= 0 && gp < 160);
#pragma unroll
        for (int c = cb; c < 128; c += 8) {
            float v = ok ? src[(size_t)c * SPAT + gp] : 0.f;
            sprev[r * 132 + c] = v;
        }
    }
    __syncthreads();

    float s  = g_s [dir * 128 + o];
    float sh = g_sh[dir * 128 + o];
    float a  = prelu_a[dir];
    const float4* wb4 = g_wk4 + dir * (32 * 3 * 128);

#pragma unroll
    for (int l = 0; l < 4; ++l) {
        int sidx = s0 + l;
        int L  = fwd ? sidx : 159 - sidx;
        const int np = 14 - 2 * l;         // positions this line (per thread)
        int q0 = p0 - (3 - l);             // global pos of j=0

        // stage pre row for this line (coalesced). rows 0..15 <-> gp base..base+15
        {
            const float* src = pb + (size_t)L * 160;
            int r  = t & 15;
            int cb = t >> 4;
            int gp = base + r;
            bool ok = (gp >= 0 && gp < 160);
#pragma unroll
            for (int c = cb; c < 128; c += 8) {
                float v = ok ? src[(size_t)c * SPAT + gp] : 0.f;
                spre[r * 132 + c] = v;
            }
        }

        float2 acc[14];
#pragma unroll
        for (int j = 0; j < np; ++j) acc[j] = make_float2(0.f, 0.f);

        if (sidx > 0) {
            int row0 = l;
            float4 K0 = wb4[0 * 128 + o], K1 = wb4[1 * 128 + o], K2 = wb4[2 * 128 + o];
            for (int cp2 = 0; cp2 < 32; ++cp2) {
                int ng = (cp2 < 31) ? cp2 + 1 : 31;
                float4 N0 = wb4[(ng * 3 + 0) * 128 + o];
                float4 N1 = wb4[(ng * 3 + 1) * 128 + o];
                float4 N2 = wb4[(ng * 3 + 2) * 128 + o];

                const float* col = sprev + 4 * cp2;
                float4 V0 = *reinterpret_cast<const float4*>(col + (row0    ) * 132);
                float4 V1 = *reinterpret_cast<const float4*>(col + (row0 + 1) * 132);
                float4 V2 = *reinterpret_cast<const float4*>(col + (row0 + 2) * 132);
#pragma unroll
                for (int j = 0; j < np; ++j) {
                    float4 VN = *reinterpret_cast<const float4*>(col + (row0 + j + 3) * 132);
                    acc[j] = ffma2f(lo2(V0), lo2(K0), acc[j]);
                    acc[j] = ffma2f(hi2(V0), hi2(K0), acc[j]);
                    acc[j] = ffma2f(lo2(V1), lo2(K1), acc[j]);
                    acc[j] = ffma2f(hi2(V1), hi2(K1), acc[j]);
                    acc[j] = ffma2f(lo2(V2), lo2(K2), acc[j]);
                    acc[j] = ffma2f(hi2(V2), hi2(K2), acc[j]);
                    V0 = V1; V1 = V2; V2 = VN;
                }
                K0 = N0; K1 = N1; K2 = N2;
            }
        }
        __syncthreads();   // spre visible; sprev reads done

        // epilogue: y = PReLU(BN(pre + conv)) into scur (rows 1+l .. 14-l)
#pragma unroll
        for (int j = 0; j < np; ++j) {
            int gp  = q0 + j;
            int row = 1 + l + j;
            float y = 0.f;
            if (gp >= 0 && gp < 160) {
                float h = spre[row * 132 + o] + acc[j].x + acc[j].y;
                y = h * s + sh;
                y = (y >= 0.f) ? y : a * y;
            }
            scur[row * 132 + o] = y;
        }
        __syncthreads();   // scur complete

        // coalesced writer: owned gp in [p0, p0+8) = rows 4..11
        {
            int r  = t & 7;
            int cg = t >> 3;               // 16 channel-groups
            int gp = p0 + r;
            float* dst = yb + (size_t)L * 160 + gp;
#pragma unroll
            for (int c = cg; c < 128; c += 16)
                dst[(size_t)c * SPAT] = scur[(r + 4) * 132 + c];
        }
        float* t_ = sprev; sprev = scur; scur = t_;
    }
}

// ---------------------------------------------------------------------------
// Fusion: out[o] = relu( sum_q feat[q]*wf[q][o]*finv + fc[o] ), q = dir*128+c.
// dirs 0,1 from g_feat (canonical), dirs 2,3 from g_tmp (transposed back).
// ---------------------------------------------------------------------------
__global__ void __launch_bounds__(128) fus_kernel(float* __restrict__ out) {
    int bx   = blockIdx.x;          // 12800 = 8*160*10
    int tile = bx % 10;
    int hh   = (bx / 10) % 160;
    int b    = bx / 1600;
    int t  = threadIdx.x;
    int ol = t & 63;
    int wg = t >> 6;
    int w0 = tile * 16;

    __shared__ __align__(16) float fs[16 * 16];   // [j][c]
    float2 acc0[8], acc1[8];
#pragma unroll
    for (int j = 0; j < 8; ++j) { acc0[j] = make_float2(0.f, 0.f); acc1[j] = make_float2(0.f, 0.f); }

    for (int q0 = 0; q0 < 512; q0 += 16) {
        for (int i = t; i < 256; i += 128) {
            int c = i >> 4, j = i & 15;
            int q = q0 + c; int dir = q >> 7; int cc = q & 127;
            const float* fp = (dir < 2)
                ? (g_feat + ((size_t)(dir * 8 + b) * 128 + cc) * SPAT)
                : (g_tmp  + ((size_t)((dir - 2) * 8 + b) * 128 + cc) * SPAT);
            fs[j * 16 + c] = fp[hh * 160 + w0 + j];
        }
        __syncthreads();

        int qb = q0 >> 1;
#pragma unroll
        for (int cp2 = 0; cp2 < 4; ++cp2) {
            int qp = qb + 2 * cp2;
            float2 wa0 = g_wfp[qp * 128 + ol];
            float2 wb0 = g_wfp[qp * 128 + ol + 64];
            float2 wa1 = g_wfp[(qp + 1) * 128 + ol];
            float2 wb1 = g_wfp[(qp + 1) * 128 + ol + 64];
#pragma unroll
            for (int jj = 0; jj < 8; ++jj) {
                float4 V = *reinterpret_cast<const float4*>(fs + (wg * 8 + jj) * 16 + 4 * cp2);
                acc0[jj] = ffma2f(lo2(V), wa0, acc0[jj]);
                acc0[jj] = ffma2f(hi2(V), wa1, acc0[jj]);
                acc1[jj] = ffma2f(lo2(V), wb0, acc1[jj]);
                acc1[jj] = ffma2f(hi2(V), wb1, acc1[jj]);
            }
        }
        __syncthreads();
    }

    float c0v = g_fc[ol], c1v = g_fc[ol + 64];
    float* ob0 = out + (((size_t)b * 128 + ol     ) * 160 + hh) * 160 + w0 + wg * 8;
    float* ob1 = out + (((size_t)b * 128 + ol + 64) * 160 + hh) * 160 + w0 + wg * 8;
#pragma unroll
    for (int j4 = 0; j4 < 8; j4 += 4) {
        float4 r;
        r.x = fmaxf(acc0[j4    ].x + acc0[j4    ].y + c0v, 0.f);
        r.y = fmaxf(acc0[j4 + 1].x + acc0[j4 + 1].y + c0v, 0.f);
        r.z = fmaxf(acc0[j4 + 2].x + acc0[j4 + 2].y + c0v, 0.f);
        r.w = fmaxf(acc0[j4 + 3].x + acc0[j4 + 3].y + c0v, 0.f);
        *reinterpret_cast<float4*>(ob0 + j4) = r;
        float4 q;
        q.x = fmaxf(acc1[j4    ].x + acc1[j4    ].y + c1v, 0.f);
        q.y = fmaxf(acc1[j4 + 1].x + acc1[j4 + 1].y + c1v, 0.f);
        q.z = fmaxf(acc1[j4 + 2].x + acc1[j4 + 2].y + c1v, 0.f);
        q.w = fmaxf(acc1[j4 + 3].x + acc1[j4 + 3].y + c1v, 0.f);
        *reinterpret_cast<float4*>(ob1 + j4) = q;
    }
}

// ---------------------------------------------------------------------------
extern "C" void kernel_launch(void* const* d_in, const int* in_sizes, int n_in,
                              void* d_out, int out_size) {
    const float* x         = (const float*)d_in[0];
    const float* kernels   = (const float*)d_in[1];
    const float* biases    = (const float*)d_in[2];
    const float* bn_gamma  = (const float*)d_in[3];
    const float* bn_beta   = (const float*)d_in[4];
    const float* bn_mean   = (const float*)d_in[5];
    const float* bn_var    = (const float*)d_in[6];
    const float* prelu_a   = (const float*)d_in[7];
    const float* fus_w     = (const float*)d_in[8];
    const float* fus_b     = (const float*)d_in[9];
    const float* fbn_gamma = (const float*)d_in[10];
    const float* fbn_beta  = (const float*)d_in[11];
    const float* fbn_mean  = (const float*)d_in[12];
    const float* fbn_var   = (const float*)d_in[13];

    // our idx 0..2; harness prefix = 2 -> ncu -s 5 captures our idx 3 = step4(g=0)
    prep_kernel<<<128, 256>>>(kernels, bn_gamma, bn_beta, bn_mean, bn_var,
                              fus_w, fus_b, fbn_gamma, fbn_beta, fbn_mean, fbn_var);

    transpose_kernel<<<8 * 128 * 25, dim3(32, 8)>>>(x, 0);

    pre_kernel<<<25600, 256>>>(x, biases);

    // 40 fused recurrence launches; each advances all dirs/batches by 4 lines
    for (int g = 0; g < 40; ++g)
        step4_kernel<<<640, 128>>>(prelu_a, g);

    // bring dirs 2,3 back to canonical [h][w] layout for fusion
    transpose_kernel<<<2 * 8 * 128 * 25, dim3(32, 8)>>>(x, 1);

    // fused 1x1 conv + BN + ReLU
    fus_kernel<<<12800, 128>>>((float*)d_out);
}

// round 16
// speedup vs baseline: 1.3828x; 1.1005x over previous
#include <cuda_runtime.h>
#include <cuda_bf16.h>
#include <cstdint>

// ---------------------------------------------------------------------------
// SpatialConvModule (SCNN-style): 4 directional recurrent 3-tap convs + fusion
// B=8, C=128, H=W=160. All fp32, packed f32x2 FMA (sm_103a).
// R16 == R14 resubmit #2 (R14: device-busy at harness init; R15: broker
//      container failed twice — both infra-class, kernel never executed):
//      pre double-buffered staging (hide L2 latency); fus register-tiled
//      128x128 GEMM block (8o x 8p per thread, smem W+F tiles).
// ---------------------------------------------------------------------------

#define EPSV 1e-5f
#define SPAT 25600            // 160*160

// ---- static device scratch (allocation-free rule) -------------------------
__device__ float  g_pre [4ull*8*128*160*160];  // pre-activations (read-only in steps)
__device__ float  g_feat[4ull*8*128*160*160];  // recurrence outputs (features)
__device__ float  g_xT [8ull*128*160*160];     // x transposed per (b,c): [w][h]
__device__ float  g_tmp[2ull*8*128*160*160];   // dirs 2,3 feat transposed back
__device__ float4 g_wk4[4*32*3*128];           // [dir][cp2][tap][o]: channels 4cp2..4cp2+3
__device__ float  g_wfT[512*128];              // [q][o], fus weights pre-scaled by fbn inv
__device__ float  g_s[512], g_sh[512], g_fc[128];

// packed fp32x2 fma: d = a*b + c (elementwise on both halves)
__device__ __forceinline__ float2 ffma2f(float2 a, float2 b, float2 c) {
    float2 d;
    asm("fma.rn.f32x2 %0, %1, %2, %3;"
        : "=l"(reinterpret_cast<unsigned long long&>(d))
        : "l"(reinterpret_cast<unsigned long long&>(a)),
          "l"(reinterpret_cast<unsigned long long&>(b)),
          "l"(reinterpret_cast<unsigned long long&>(c)));
    return d;
}
__device__ __forceinline__ float2 lo2(const float4& v) { return make_float2(v.x, v.y); }
__device__ __forceinline__ float2 hi2(const float4& v) { return make_float2(v.z, v.w); }

// ---------------------------------------------------------------------------
// Prep: float4 conv-weight table, transposed pre-scaled fusion weights,
// BN folded into scale/shift.
// ---------------------------------------------------------------------------
__global__ void prep_kernel(const float* __restrict__ kern,
                            const float* __restrict__ bg, const float* __restrict__ bb,
                            const float* __restrict__ bm, const float* __restrict__ bv,
                            const float* __restrict__ fw, const float* __restrict__ fb,
                            const float* __restrict__ fg, const float* __restrict__ fbeta,
                            const float* __restrict__ fm, const float* __restrict__ fv) {
    const int NW4 = 49152, NWT = 65536;   // 4*32*3*128, 512*128
    int total = NW4 + NWT + 512 + 128;
    for (int i = blockIdx.x * blockDim.x + threadIdx.x; i < total;
         i += gridDim.x * blockDim.x) {
        if (i < NW4) {
            int dir = i / 12288; int r = i % 12288;
            int cp2 = r / 384;   int r2 = r % 384;
            int tap = r2 / 128;  int o = r2 % 128;
            int c0 = 4 * cp2;
            float w[4];
#pragma unroll
            for (int q = 0; q < 4; ++q) {
                int c = c0 + q;
                if (dir < 2)   // 1x3 kernel: kh=1, kw=tap
                    w[q] = kern[(((dir*128 + o)*128 + c)*3 + 1)*3 + tap];
                else           // 3x1 kernel: kh=tap, kw=1
                    w[q] = kern[(((dir*128 + o)*128 + c)*3 + tap)*3 + 1];
            }
            g_wk4[i] = make_float4(w[0], w[1], w[2], w[3]);
        } else if (i < NW4 + NWT) {
            int idx = i - NW4; int q = idx / 128; int o = idx % 128;
            float fs = fg[o] * rsqrtf(fv[o] + EPSV);
            g_wfT[idx] = fw[o*512 + q] * fs;
        } else if (i < NW4 + NWT + 512) {
            int idx = i - NW4 - NWT;
            float s = bg[idx] * rsqrtf(bv[idx] + EPSV);
            g_s[idx] = s; g_sh[idx] = bb[idx] - bm[idx] * s;
        } else {
            int o = i - NW4 - NWT - 512;
            float fs = fg[o] * rsqrtf(fv[o] + EPSV);
            g_fc[o] = fb[o] * fs + fbeta[o] - fm[o] * fs;
        }
    }
}

// ---------------------------------------------------------------------------
// Tiled 160x160 transpose, M independent matrices.
// mode 0: src_x -> g_xT (M = 8*128)
// mode 1: g_feat[dirs 2,3] -> g_tmp (M = 2*8*128)
// ---------------------------------------------------------------------------
__global__ void transpose_kernel(const float* __restrict__ src_x, int mode) {
    __shared__ float t[32][33];
    int m  = blockIdx.x / 25;
    int tl = blockIdx.x % 25;
    int r0 = (tl / 5) * 32, c0 = (tl % 5) * 32;
    const float* s;
    float* d;
    if (mode == 0) { s = src_x  + (size_t)m * SPAT;              d = g_xT  + (size_t)m * SPAT; }
    else           { s = g_feat + (size_t)(16*128 + m) * SPAT;   d = g_tmp + (size_t)m * SPAT; }
    int x = threadIdx.x;
    for (int y = threadIdx.y; y < 32; y += 8)
        t[y][x] = s[(r0 + y) * 160 + c0 + x];
    __syncthreads();
    for (int y = threadIdx.y; y < 32; y += 8)
        d[(c0 + y) * 160 + r0 + x] = t[x][y];
}

// ---------------------------------------------------------------------------
// Pre kernel: out[line][p] = bias + sum_{c,d} in[c][line][p-1+d]*K
// dirs {0,1} read x (line=h, p=w); {2,3} read g_xT.
// Block: 256 threads = 128 o-channels x 2 position-halves (16 positions each).
// Double-buffered staging: next 16-channel chunk prefetched to registers
// before compute, stored to the other smem buffer after.
// ---------------------------------------------------------------------------
__global__ void __launch_bounds__(256) pre_kernel(const float* __restrict__ x,
                                                  const float* __restrict__ biases) {
    int bx   = blockIdx.x;          // 25600 = 4*8*160*5
    int tile = bx % 5;
    int line = (bx / 5) % 160;
    int b    = (bx / 800) % 8;
    int dir  = bx / 6400;
    int t    = threadIdx.x;
    int o    = t & 127;
    int half = t >> 7;
    int p0   = tile * 32;
    int jb   = half * 16;

    const float* src = ((dir < 2) ? x : g_xT) + (size_t)(b * 128) * SPAT;
    __shared__ __align__(16) float sb[2][35 * 20];  // ping-pong [p(34)][c(16)], stride 20

    float2 acc[16];
#pragma unroll
    for (int j = 0; j < 16; ++j) acc[j] = make_float2(0.f, 0.f);

    const float4* wb4 = g_wk4 + dir * (32 * 3 * 128);
    int sc = t >> 4, lane = t & 15;
    const float* srcc = src + (size_t)sc * SPAT + line * 160;   // channel sc row

    // stage chunk 0 into sb[0]
    {
#pragma unroll
        for (int pp = lane; pp < 34; pp += 16) {
            int pos = p0 - 1 + pp;
            float v = 0.f;
            if (pos >= 0 && pos < 160) v = srcc[pos];
            sb[0][pp * 20 + sc] = v;
        }
    }
    __syncthreads();

    float4 K0 = wb4[0 * 128 + o], K1 = wb4[1 * 128 + o], K2 = wb4[2 * 128 + o];
    int gcp2 = 0;
    for (int c0p = 0; c0p < 8; ++c0p) {
        int cur = c0p & 1;

        // prefetch next chunk into registers (in flight during compute)
        float pf0 = 0.f, pf1 = 0.f, pf2 = 0.f;
        if (c0p < 7) {
            const float* srow = srcc + (size_t)(16 * (c0p + 1)) * SPAT;
            int pos0 = p0 - 1 + lane;
            if (pos0 >= 0 && pos0 < 160) pf0 = srow[pos0];
            int pos1 = pos0 + 16;                      // always in [15,158]
            pf1 = srow[pos1];
            if (lane < 2) {
                int pos2 = pos0 + 32;
                if (pos2 < 160) pf2 = srow[pos2];
            }
        }

#pragma unroll
        for (int cp2l = 0; cp2l < 4; ++cp2l) {
            int ng = (gcp2 < 31) ? gcp2 + 1 : 31;
            float4 N0 = wb4[(ng * 3 + 0) * 128 + o];
            float4 N1 = wb4[(ng * 3 + 1) * 128 + o];
            float4 N2 = wb4[(ng * 3 + 2) * 128 + o];

            const float* col = sb[cur] + 4 * cp2l;
            float4 V0 = *reinterpret_cast<const float4*>(col + (jb + 0) * 20);
            float4 V1 = *reinterpret_cast<const float4*>(col + (jb + 1) * 20);
            float4 V2 = *reinterpret_cast<const float4*>(col + (jb + 2) * 20);
#pragma unroll
            for (int j = 0; j < 16; ++j) {
                float4 VN = *reinterpret_cast<const float4*>(col + (jb + j + 3) * 20);
                acc[j] = ffma2f(lo2(V0), lo2(K0), acc[j]);
                acc[j] = ffma2f(hi2(V0), hi2(K0), acc[j]);
                acc[j] = ffma2f(lo2(V1), lo2(K1), acc[j]);
                acc[j] = ffma2f(hi2(V1), hi2(K1), acc[j]);
                acc[j] = ffma2f(lo2(V2), lo2(K2), acc[j]);
                acc[j] = ffma2f(hi2(V2), hi2(K2), acc[j]);
                V0 = V1; V1 = V2; V2 = VN;
            }
            K0 = N0; K1 = N1; K2 = N2;
            ++gcp2;
        }

        if (c0p < 7) {
            float* d = sb[cur ^ 1];
            d[lane * 20 + sc]        = pf0;
            d[(lane + 16) * 20 + sc] = pf1;
            if (lane < 2) d[(lane + 32) * 20 + sc] = pf2;
        }
        __syncthreads();
    }

    float bias = biases[dir * 128 + o];
    float* op = g_pre + ((size_t)(dir * 8 + b) * 128 + o) * SPAT + line * 160 + p0 + jb;
#pragma unroll
    for (int j4 = 0; j4 < 16; j4 += 4) {
        float4 r;
        r.x = acc[j4    ].x + acc[j4    ].y + bias;
        r.y = acc[j4 + 1].x + acc[j4 + 1].y + bias;
        r.z = acc[j4 + 2].x + acc[j4 + 2].y + bias;
        r.w = acc[j4 + 3].x + acc[j4 + 3].y + bias;
        *reinterpret_cast<float4*>(op + j4) = r;
    }
}

// ---------------------------------------------------------------------------
// Fused 4-line recurrence step. 640 blocks x 128 threads (thread = o).
// Tile width 8; line l computes np = 14-2l positions per thread (halo
// recompute). Weights: 3 LDG.128 per cp2 (float4 table), prefetch +1.
// pre staged per line into SMEM (coalesced LDG); y written back via
// transposing coalesced writer.
// ---------------------------------------------------------------------------
__global__ void __launch_bounds__(128) step4_kernel(const float* __restrict__ prelu_a,
                                                    int g) {
    int bx   = blockIdx.x;
    int dir  = bx & 3;
    int b    = (bx >> 2) & 7;
    int tile = bx >> 5;                    // 0..19
    int o    = threadIdx.x;
    int t    = threadIdx.x;
    int p0   = tile * 8;
    int base = p0 - 4;                     // buffer row r <-> global pos base+r

    bool fwd = (dir == 0) || (dir == 2);
    const float* pb = g_pre  + (size_t)(dir * 8 + b) * 128 * SPAT;
    float*       yb = g_feat + (size_t)(dir * 8 + b) * 128 * SPAT;

    __shared__ __align__(16) float buf0[17 * 132];
    __shared__ __align__(16) float buf1[17 * 132];
    __shared__ __align__(16) float spre[16 * 132];
    float* sprev = buf0;
    float* scur  = buf1;

    int s0 = 4 * g;
    // stage y of line (s0-1): coalesced (lane = position, loop channels)
    {
        int sp = s0 - 1;
        int Lp = fwd ? sp : 159 - sp;
        const float* src = yb + (size_t)(Lp < 0 ? 0 : Lp) * 160;
        int r  = t & 15;
        int cb = t >> 4;                   // 8 channel-groups
        int gp = base + r;
        bool ok = (g > 0 && gp >= 0 && gp < 160);
#pragma unroll
        for (int c = cb; c < 128; c += 8) {
            float v = ok ? src[(size_t)c * SPAT + gp] : 0.f;
            sprev[r * 132 + c] = v;
        }
    }
    __syncthreads();

    float s  = g_s [dir * 128 + o];
    float sh = g_sh[dir * 128 + o];
    float a  = prelu_a[dir];
    const float4* wb4 = g_wk4 + dir * (32 * 3 * 128);

#pragma unroll
    for (int l = 0; l < 4; ++l) {
        int sidx = s0 + l;
        int L  = fwd ? sidx : 159 - sidx;
        const int np = 14 - 2 * l;         // positions this line (per thread)
        int q0 = p0 - (3 - l);             // global pos of j=0

        // stage pre row for this line (coalesced). rows 0..15 <-> gp base..base+15
        {
            const float* src = pb + (size_t)L * 160;
            int r  = t & 15;
            int cb = t >> 4;
            int gp = base + r;
            bool ok = (gp >= 0 && gp < 160);
#pragma unroll
            for (int c = cb; c < 128; c += 8) {
                float v = ok ? src[(size_t)c * SPAT + gp] : 0.f;
                spre[r * 132 + c] = v;
            }
        }

        float2 acc[14];
#pragma unroll
        for (int j = 0; j < np; ++j) acc[j] = make_float2(0.f, 0.f);

        if (sidx > 0) {
            int row0 = l;
            float4 K0 = wb4[0 * 128 + o], K1 = wb4[1 * 128 + o], K2 = wb4[2 * 128 + o];
            for (int cp2 = 0; cp2 < 32; ++cp2) {
                int ng = (cp2 < 31) ? cp2 + 1 : 31;
                float4 N0 = wb4[(ng * 3 + 0) * 128 + o];
                float4 N1 = wb4[(ng * 3 + 1) * 128 + o];
                float4 N2 = wb4[(ng * 3 + 2) * 128 + o];

                const float* col = sprev + 4 * cp2;
                float4 V0 = *reinterpret_cast<const float4*>(col + (row0    ) * 132);
                float4 V1 = *reinterpret_cast<const float4*>(col + (row0 + 1) * 132);
                float4 V2 = *reinterpret_cast<const float4*>(col + (row0 + 2) * 132);
#pragma unroll
                for (int j = 0; j < np; ++j) {
                    float4 VN = *reinterpret_cast<const float4*>(col + (row0 + j + 3) * 132);
                    acc[j] = ffma2f(lo2(V0), lo2(K0), acc[j]);
                    acc[j] = ffma2f(hi2(V0), hi2(K0), acc[j]);
                    acc[j] = ffma2f(lo2(V1), lo2(K1), acc[j]);
                    acc[j] = ffma2f(hi2(V1), hi2(K1), acc[j]);
                    acc[j] = ffma2f(lo2(V2), lo2(K2), acc[j]);
                    acc[j] = ffma2f(hi2(V2), hi2(K2), acc[j]);
                    V0 = V1; V1 = V2; V2 = VN;
                }
                K0 = N0; K1 = N1; K2 = N2;
            }
        }
        __syncthreads();   // spre visible; sprev reads done

        // epilogue: y = PReLU(BN(pre + conv)) into scur (rows 1+l .. 14-l)
#pragma unroll
        for (int j = 0; j < np; ++j) {
            int gp  = q0 + j;
            int row = 1 + l + j;
            float y = 0.f;
            if (gp >= 0 && gp < 160) {
                float h = spre[row * 132 + o] + acc[j].x + acc[j].y;
                y = h * s + sh;
                y = (y >= 0.f) ? y : a * y;
            }
            scur[row * 132 + o] = y;
        }
        __syncthreads();   // scur complete

        // coalesced writer: owned gp in [p0, p0+8) = rows 4..11
        {
            int r  = t & 7;
            int cg = t >> 3;               // 16 channel-groups
            int gp = p0 + r;
            float* dst = yb + (size_t)L * 160 + gp;
#pragma unroll
            for (int c = cg; c < 128; c += 16)
                dst[(size_t)c * SPAT] = scur[(r + 4) * 132 + c];
        }
        float* t_ = sprev; sprev = scur; scur = t_;
    }
}

// ---------------------------------------------------------------------------
// Fusion GEMM: out[b][o][p] = relu(sum_q WfT[q][o]*F[q][b][p] + fc[o]).
// Grid: 8 b * 200 p-tiles = 1600 blocks x 256 threads.
// Block tile: 128 o x 128 p, K in 32 phases of 16 q.
// Thread tile: 8 o x 8 p (acc[8][4] p-paired float2).
// ---------------------------------------------------------------------------
__global__ void __launch_bounds__(256) fus_kernel(float* __restrict__ out) {
    int bx = blockIdx.x;            // 1600
    int b  = bx / 200;
    int p0 = (bx % 200) * 128;
    int t  = threadIdx.x;
    int lane = t & 31, warp = t >> 5;
    int wo = warp & 1, wp = warp >> 1;     // o-half, p-quarter
    int lo = lane & 7, lp = lane >> 3;     // o-oct, p-oct
    int ob = wo * 64 + lo * 8;
    int pb = wp * 32 + lp * 8;

    __shared__ __align__(16) float Fs[16 * 128];
    __shared__ __align__(16) float Ws[16 * 128];

    float2 acc[8][4];
#pragma unroll
    for (int oi = 0; oi < 8; ++oi)
#pragma unroll
        for (int pi = 0; pi < 4; ++pi) acc[oi][pi] = make_float2(0.f, 0.f);

    for (int phase = 0; phase < 32; ++phase) {
        int q0 = phase * 16;
#pragma unroll
        for (int i = 0; i < 2; ++i) {
            int fl = i * 256 + t;          // 0..511
            int q  = fl >> 5;              // 0..15
            int pq = fl & 31;              // float4 slot
            int qq = q0 + q;
            int dirq = qq >> 7, cc = qq & 127;
            const float* fp = (dirq < 2)
                ? (g_feat + ((size_t)(dirq * 8 + b) * 128 + cc) * SPAT)
                : (g_tmp  + ((size_t)((dirq - 2) * 8 + b) * 128 + cc) * SPAT);
            *reinterpret_cast<float4*>(&Fs[q * 128 + pq * 4]) =
                *reinterpret_cast<const float4*>(fp + p0 + pq * 4);
            *reinterpret_cast<float4*>(&Ws[q * 128 + pq * 4]) =
                *reinterpret_cast<const float4*>(g_wfT + (size_t)qq * 128 + pq * 4);
        }
        __syncthreads();

#pragma unroll
        for (int q = 0; q < 16; ++q) {
            float4 W0 = *reinterpret_cast<const float4*>(&Ws[q * 128 + ob]);
            float4 W1 = *reinterpret_cast<const float4*>(&Ws[q * 128 + ob + 4]);
            float4 V0 = *reinterpret_cast<const float4*>(&Fs[q * 128 + pb]);
            float4 V1 = *reinterpret_cast<const float4*>(&Fs[q * 128 + pb + 4]);
            float2 vp[4] = { lo2(V0), hi2(V0), lo2(V1), hi2(V1) };
            float wv[8] = { W0.x, W0.y, W0.z, W0.w, W1.x, W1.y, W1.z, W1.w };
#pragma unroll
            for (int oi = 0; oi < 8; ++oi) {
                float2 ws = make_float2(wv[oi], wv[oi]);
#pragma unroll
                for (int pi = 0; pi < 4; ++pi)
                    acc[oi][pi] = ffma2f(vp[pi], ws, acc[oi][pi]);
            }
        }
        __syncthreads();
    }

#pragma unroll
    for (int oi = 0; oi < 8; ++oi) {
        int o = ob + oi;
        float c = g_fc[o];
        float* dst = out + ((size_t)b * 128 + o) * SPAT + p0 + pb;
        float4 r0, r1;
        r0.x = fmaxf(acc[oi][0].x + c, 0.f);
        r0.y = fmaxf(acc[oi][0].y + c, 0.f);
        r0.z = fmaxf(acc[oi][1].x + c, 0.f);
        r0.w = fmaxf(acc[oi][1].y + c, 0.f);
        r1.x = fmaxf(acc[oi][2].x + c, 0.f);
        r1.y = fmaxf(acc[oi][2].y + c, 0.f);
        r1.z = fmaxf(acc[oi][3].x + c, 0.f);
        r1.w = fmaxf(acc[oi][3].y + c, 0.f);
        *reinterpret_cast<float4*>(dst)     = r0;
        *reinterpret_cast<float4*>(dst + 4) = r1;
    }
}

// ---------------------------------------------------------------------------
extern "C" void kernel_launch(void* const* d_in, const int* in_sizes, int n_in,
                              void* d_out, int out_size) {
    const float* x         = (const float*)d_in[0];
    const float* kernels   = (const float*)d_in[1];
    const float* biases    = (const float*)d_in[2];
    const float* bn_gamma  = (const float*)d_in[3];
    const float* bn_beta   = (const float*)d_in[4];
    const float* bn_mean   = (const float*)d_in[5];
    const float* bn_var    = (const float*)d_in[6];
    const float* prelu_a   = (const float*)d_in[7];
    const float* fus_w     = (const float*)d_in[8];
    const float* fus_b     = (const float*)d_in[9];
    const float* fbn_gamma = (const float*)d_in[10];
    const float* fbn_beta  = (const float*)d_in[11];
    const float* fbn_mean  = (const float*)d_in[12];
    const float* fbn_var   = (const float*)d_in[13];

    // our idx 0..2; harness prefix = 2 -> ncu -s 5 captures our idx 3 = step4(g=0)
    prep_kernel<<<128, 256>>>(kernels, bn_gamma, bn_beta, bn_mean, bn_var,
                              fus_w, fus_b, fbn_gamma, fbn_beta, fbn_mean, fbn_var);

    transpose_kernel<<<8 * 128 * 25, dim3(32, 8)>>>(x, 0);

    pre_kernel<<<25600, 256>>>(x, biases);

    // 40 fused recurrence launches; each advances all dirs/batches by 4 lines
    for (int g = 0; g < 40; ++g)
        step4_kernel<<<640, 128>>>(prelu_a, g);

    // bring dirs 2,3 back to canonical [h][w] layout for fusion
    transpose_kernel<<<2 * 8 * 128 * 25, dim3(32, 8)>>>(x, 1);

    // fused 1x1 conv + BN + ReLU (register-tiled GEMM)
    fus_kernel<<<1600, 256>>>((float*)d_out);
}

// round 17
// speedup vs baseline: 1.3864x; 1.0026x over previous
#include <cuda_runtime.h>
#include <cuda_bf16.h>
#include <cstdint>

// ---------------------------------------------------------------------------
// SpatialConvModule (SCNN-style): 4 directional recurrent 3-tap convs + fusion
// B=8, C=128, H=W=160. All fp32, packed f32x2 FMA (sm_103a).
// R17: step4 tile 8->16 (320 blocks; halves weight-wavefronts per output),
//      noop inserted so ncu -s 5 captures pre_kernel (first pre profile
//      since the R14 rewrite).
// ---------------------------------------------------------------------------

#define EPSV 1e-5f
#define SPAT 25600            // 160*160

// ---- static device scratch (allocation-free rule) -------------------------
__device__ float  g_pre [4ull*8*128*160*160];  // pre-activations (read-only in steps)
__device__ float  g_feat[4ull*8*128*160*160];  // recurrence outputs (features)
__device__ float  g_xT [8ull*128*160*160];     // x transposed per (b,c): [w][h]
__device__ float  g_tmp[2ull*8*128*160*160];   // dirs 2,3 feat transposed back
__device__ float4 g_wk4[4*32*3*128];           // [dir][cp2][tap][o]: channels 4cp2..4cp2+3
__device__ float  g_wfT[512*128];              // [q][o], fus weights pre-scaled by fbn inv
__device__ float  g_s[512], g_sh[512], g_fc[128];

// packed fp32x2 fma: d = a*b + c (elementwise on both halves)
__device__ __forceinline__ float2 ffma2f(float2 a, float2 b, float2 c) {
    float2 d;
    asm("fma.rn.f32x2 %0, %1, %2, %3;"
        : "=l"(reinterpret_cast<unsigned long long&>(d))
        : "l"(reinterpret_cast<unsigned long long&>(a)),
          "l"(reinterpret_cast<unsigned long long&>(b)),
          "l"(reinterpret_cast<unsigned long long&>(c)));
    return d;
}
__device__ __forceinline__ float2 lo2(const float4& v) { return make_float2(v.x, v.y); }
__device__ __forceinline__ float2 hi2(const float4& v) { return make_float2(v.z, v.w); }

__global__ void noop_kernel() {}

// ---------------------------------------------------------------------------
// Prep: float4 conv-weight table, transposed pre-scaled fusion weights,
// BN folded into scale/shift.
// ---------------------------------------------------------------------------
__global__ void prep_kernel(const float* __restrict__ kern,
                            const float* __restrict__ bg, const float* __restrict__ bb,
                            const float* __restrict__ bm, const float* __restrict__ bv,
                            const float* __restrict__ fw, const float* __restrict__ fb,
                            const float* __restrict__ fg, const float* __restrict__ fbeta,
                            const float* __restrict__ fm, const float* __restrict__ fv) {
    const int NW4 = 49152, NWT = 65536;   // 4*32*3*128, 512*128
    int total = NW4 + NWT + 512 + 128;
    for (int i = blockIdx.x * blockDim.x + threadIdx.x; i < total;
         i += gridDim.x * blockDim.x) {
        if (i < NW4) {
            int dir = i / 12288; int r = i % 12288;
            int cp2 = r / 384;   int r2 = r % 384;
            int tap = r2 / 128;  int o = r2 % 128;
            int c0 = 4 * cp2;
            float w[4];
#pragma unroll
            for (int q = 0; q < 4; ++q) {
                int c = c0 + q;
                if (dir < 2)   // 1x3 kernel: kh=1, kw=tap
                    w[q] = kern[(((dir*128 + o)*128 + c)*3 + 1)*3 + tap];
                else           // 3x1 kernel: kh=tap, kw=1
                    w[q] = kern[(((dir*128 + o)*128 + c)*3 + tap)*3 + 1];
            }
            g_wk4[i] = make_float4(w[0], w[1], w[2], w[3]);
        } else if (i < NW4 + NWT) {
            int idx = i - NW4; int q = idx / 128; int o = idx % 128;
            float fs = fg[o] * rsqrtf(fv[o] + EPSV);
            g_wfT[idx] = fw[o*512 + q] * fs;
        } else if (i < NW4 + NWT + 512) {
            int idx = i - NW4 - NWT;
            float s = bg[idx] * rsqrtf(bv[idx] + EPSV);
            g_s[idx] = s; g_sh[idx] = bb[idx] - bm[idx] * s;
        } else {
            int o = i - NW4 - NWT - 512;
            float fs = fg[o] * rsqrtf(fv[o] + EPSV);
            g_fc[o] = fb[o] * fs + fbeta[o] - fm[o] * fs;
        }
    }
}

// ---------------------------------------------------------------------------
// Tiled 160x160 transpose, M independent matrices.
// mode 0: src_x -> g_xT (M = 8*128)
// mode 1: g_feat[dirs 2,3] -> g_tmp (M = 2*8*128)
// ---------------------------------------------------------------------------
__global__ void transpose_kernel(const float* __restrict__ src_x, int mode) {
    __shared__ float t[32][33];
    int m  = blockIdx.x / 25;
    int tl = blockIdx.x % 25;
    int r0 = (tl / 5) * 32, c0 = (tl % 5) * 32;
    const float* s;
    float* d;
    if (mode == 0) { s = src_x  + (size_t)m * SPAT;              d = g_xT  + (size_t)m * SPAT; }
    else           { s = g_feat + (size_t)(16*128 + m) * SPAT;   d = g_tmp + (size_t)m * SPAT; }
    int x = threadIdx.x;
    for (int y = threadIdx.y; y < 32; y += 8)
        t[y][x] = s[(r0 + y) * 160 + c0 + x];
    __syncthreads();
    for (int y = threadIdx.y; y < 32; y += 8)
        d[(c0 + y) * 160 + r0 + x] = t[x][y];
}

// ---------------------------------------------------------------------------
// Pre kernel: out[line][p] = bias + sum_{c,d} in[c][line][p-1+d]*K
// dirs {0,1} read x (line=h, p=w); {2,3} read g_xT.
// Block: 256 threads = 128 o-channels x 2 position-halves (16 positions each).
// Double-buffered staging: next 16-channel chunk prefetched to registers
// before compute, stored to the other smem buffer after.
// ---------------------------------------------------------------------------
__global__ void __launch_bounds__(256) pre_kernel(const float* __restrict__ x,
                                                  const float* __restrict__ biases) {
    int bx   = blockIdx.x;          // 25600 = 4*8*160*5
    int tile = bx % 5;
    int line = (bx / 5) % 160;
    int b    = (bx / 800) % 8;
    int dir  = bx / 6400;
    int t    = threadIdx.x;
    int o    = t & 127;
    int half = t >> 7;
    int p0   = tile * 32;
    int jb   = half * 16;

    const float* src = ((dir < 2) ? x : g_xT) + (size_t)(b * 128) * SPAT;
    __shared__ __align__(16) float sb[2][35 * 20];  // ping-pong [p(34)][c(16)], stride 20

    float2 acc[16];
#pragma unroll
    for (int j = 0; j < 16; ++j) acc[j] = make_float2(0.f, 0.f);

    const float4* wb4 = g_wk4 + dir * (32 * 3 * 128);
    int sc = t >> 4, lane = t & 15;
    const float* srcc = src + (size_t)sc * SPAT + line * 160;   // channel sc row

    // stage chunk 0 into sb[0]
    {
#pragma unroll
        for (int pp = lane; pp < 34; pp += 16) {
            int pos = p0 - 1 + pp;
            float v = 0.f;
            if (pos >= 0 && pos < 160) v = srcc[pos];
            sb[0][pp * 20 + sc] = v;
        }
    }
    __syncthreads();

    float4 K0 = wb4[0 * 128 + o], K1 = wb4[1 * 128 + o], K2 = wb4[2 * 128 + o];
    int gcp2 = 0;
    for (int c0p = 0; c0p < 8; ++c0p) {
        int cur = c0p & 1;

        // prefetch next chunk into registers (in flight during compute)
        float pf0 = 0.f, pf1 = 0.f, pf2 = 0.f;
        if (c0p < 7) {
            const float* srow = srcc + (size_t)(16 * (c0p + 1)) * SPAT;
            int pos0 = p0 - 1 + lane;
            if (pos0 >= 0 && pos0 < 160) pf0 = srow[pos0];
            int pos1 = pos0 + 16;                      // always in [15,158]
            pf1 = srow[pos1];
            if (lane < 2) {
                int pos2 = pos0 + 32;
                if (pos2 < 160) pf2 = srow[pos2];
            }
        }

#pragma unroll
        for (int cp2l = 0; cp2l < 4; ++cp2l) {
            int ng = (gcp2 < 31) ? gcp2 + 1 : 31;
            float4 N0 = wb4[(ng * 3 + 0) * 128 + o];
            float4 N1 = wb4[(ng * 3 + 1) * 128 + o];
            float4 N2 = wb4[(ng * 3 + 2) * 128 + o];

            const float* col = sb[cur] + 4 * cp2l;
            float4 V0 = *reinterpret_cast<const float4*>(col + (jb + 0) * 20);
            float4 V1 = *reinterpret_cast<const float4*>(col + (jb + 1) * 20);
            float4 V2 = *reinterpret_cast<const float4*>(col + (jb + 2) * 20);
#pragma unroll
            for (int j = 0; j < 16; ++j) {
                float4 VN = *reinterpret_cast<const float4*>(col + (jb + j + 3) * 20);
                acc[j] = ffma2f(lo2(V0), lo2(K0), acc[j]);
                acc[j] = ffma2f(hi2(V0), hi2(K0), acc[j]);
                acc[j] = ffma2f(lo2(V1), lo2(K1), acc[j]);
                acc[j] = ffma2f(hi2(V1), hi2(K1), acc[j]);
                acc[j] = ffma2f(lo2(V2), lo2(K2), acc[j]);
                acc[j] = ffma2f(hi2(V2), hi2(K2), acc[j]);
                V0 = V1; V1 = V2; V2 = VN;
            }
            K0 = N0; K1 = N1; K2 = N2;
            ++gcp2;
        }

        if (c0p < 7) {
            float* d = sb[cur ^ 1];
            d[lane * 20 + sc]        = pf0;
            d[(lane + 16) * 20 + sc] = pf1;
            if (lane < 2) d[(lane + 32) * 20 + sc] = pf2;
        }
        __syncthreads();
    }

    float bias = biases[dir * 128 + o];
    float* op = g_pre + ((size_t)(dir * 8 + b) * 128 + o) * SPAT + line * 160 + p0 + jb;
#pragma unroll
    for (int j4 = 0; j4 < 16; j4 += 4) {
        float4 r;
        r.x = acc[j4    ].x + acc[j4    ].y + bias;
        r.y = acc[j4 + 1].x + acc[j4 + 1].y + bias;
        r.z = acc[j4 + 2].x + acc[j4 + 2].y + bias;
        r.w = acc[j4 + 3].x + acc[j4 + 3].y + bias;
        *reinterpret_cast<float4*>(op + j4) = r;
    }
}

// ---------------------------------------------------------------------------
// Fused 4-line recurrence step. 320 blocks x 128 threads (thread = o).
// Tile width 16; line l computes np = 22-2l positions per thread (halo
// recompute) -> weight wavefronts per useful output HALVED vs tile 8.
// Buffer rows 0..23 <-> global pos base..base+23, base = p0-4.
// Weights: 3 LDG.128 per cp2 (float4 table), prefetch +1; L1-resident
// after line 0. pre staged per line into SMEM (coalesced LDG); y written
// back via transposing coalesced writer.
// ---------------------------------------------------------------------------
__global__ void __launch_bounds__(128) step4_kernel(const float* __restrict__ prelu_a,
                                                    int g) {
    int bx   = blockIdx.x;                 // 320 = 4 dir * 8 b * 10 tiles
    int dir  = bx & 3;
    int b    = (bx >> 2) & 7;
    int tile = bx >> 5;                    // 0..9
    int o    = threadIdx.x;
    int t    = threadIdx.x;
    int p0   = tile * 16;
    int base = p0 - 4;                     // buffer row r <-> global pos base+r

    bool fwd = (dir == 0) || (dir == 2);
    const float* pb = g_pre  + (size_t)(dir * 8 + b) * 128 * SPAT;
    float*       yb = g_feat + (size_t)(dir * 8 + b) * 128 * SPAT;

    __shared__ __align__(16) float buf0[24 * 132];
    __shared__ __align__(16) float buf1[24 * 132];
    __shared__ __align__(16) float spre[24 * 132];
    float* sprev = buf0;
    float* scur  = buf1;

    int s0 = 4 * g;
    // stage y of line (s0-1): coalesced (lane = position, loop channels)
    {
        int sp = s0 - 1;
        int Lp = fwd ? sp : 159 - sp;
        const float* src = yb + (size_t)(Lp < 0 ? 0 : Lp) * 160;
        int r  = t & 31;
        int cb = t >> 5;                   // 4 channel-groups
        if (r < 24) {
            int gp = base + r;
            bool ok = (g > 0 && gp >= 0 && gp < 160);
#pragma unroll
            for (int c = cb; c < 128; c += 4) {
                float v = ok ? src[(size_t)c * SPAT + gp] : 0.f;
                sprev[r * 132 + c] = v;
            }
        }
    }
    __syncthreads();

    float s  = g_s [dir * 128 + o];
    float sh = g_sh[dir * 128 + o];
    float a  = prelu_a[dir];
    const float4* wb4 = g_wk4 + dir * (32 * 3 * 128);

#pragma unroll
    for (int l = 0; l < 4; ++l) {
        int sidx = s0 + l;
        int L  = fwd ? sidx : 159 - sidx;
        const int np = 22 - 2 * l;         // positions this line (per thread)
        int q0 = p0 - (3 - l);             // global pos of j=0 (row 1+l)

        // stage pre row for this line (coalesced). rows 0..23 <-> gp base..+23
        {
            const float* src = pb + (size_t)L * 160;
            int r  = t & 31;
            int cb = t >> 5;
            if (r < 24) {
                int gp = base + r;
                bool ok = (gp >= 0 && gp < 160);
#pragma unroll
                for (int c = cb; c < 128; c += 4) {
                    float v = ok ? src[(size_t)c * SPAT + gp] : 0.f;
                    spre[r * 132 + c] = v;
                }
            }
        }

        float2 acc[22];
#pragma unroll
        for (int j = 0; j < np; ++j) acc[j] = make_float2(0.f, 0.f);

        if (sidx > 0) {
            int row0 = l;
            float4 K0 = wb4[0 * 128 + o], K1 = wb4[1 * 128 + o], K2 = wb4[2 * 128 + o];
            for (int cp2 = 0; cp2 < 32; ++cp2) {
                int ng = (cp2 < 31) ? cp2 + 1 : 31;
                float4 N0 = wb4[(ng * 3 + 0) * 128 + o];
                float4 N1 = wb4[(ng * 3 + 1) * 128 + o];
                float4 N2 = wb4[(ng * 3 + 2) * 128 + o];

                const float* col = sprev + 4 * cp2;
                float4 V0 = *reinterpret_cast<const float4*>(col + (row0    ) * 132);
                float4 V1 = *reinterpret_cast<const float4*>(col + (row0 + 1) * 132);
                float4 V2 = *reinterpret_cast<const float4*>(col + (row0 + 2) * 132);
#pragma unroll
                for (int j = 0; j < np; ++j) {
                    float4 VN = *reinterpret_cast<const float4*>(col + (row0 + j + 3) * 132);
                    acc[j] = ffma2f(lo2(V0), lo2(K0), acc[j]);
                    acc[j] = ffma2f(hi2(V0), hi2(K0), acc[j]);
                    acc[j] = ffma2f(lo2(V1), lo2(K1), acc[j]);
                    acc[j] = ffma2f(hi2(V1), hi2(K1), acc[j]);
                    acc[j] = ffma2f(lo2(V2), lo2(K2), acc[j]);
                    acc[j] = ffma2f(hi2(V2), hi2(K2), acc[j]);
                    V0 = V1; V1 = V2; V2 = VN;
                }
                K0 = N0; K1 = N1; K2 = N2;
            }
        }
        __syncthreads();   // spre visible; sprev reads done

        // epilogue: y = PReLU(BN(pre + conv)) into scur (rows 1+l .. 22-l)
#pragma unroll
        for (int j = 0; j < np; ++j) {
            int gp  = q0 + j;
            int row = 1 + l + j;
            float y = 0.f;
            if (gp >= 0 && gp < 160) {
                float h = spre[row * 132 + o] + acc[j].x + acc[j].y;
                y = h * s + sh;
                y = (y >= 0.f) ? y : a * y;
            }
            scur[row * 132 + o] = y;
        }
        __syncthreads();   // scur complete

        // coalesced writer: owned gp in [p0, p0+16) = rows 4..19
        {
            int r  = t & 15;
            int cg = t >> 4;               // 8 channel-groups
            int gp = p0 + r;
            float* dst = yb + (size_t)L * 160 + gp;
#pragma unroll
            for (int c = cg; c < 128; c += 8)
                dst[(size_t)c * SPAT] = scur[(r + 4) * 132 + c];
        }
        float* t_ = sprev; sprev = scur; scur = t_;
    }
}

// ---------------------------------------------------------------------------
// Fusion GEMM: out[b][o][p] = relu(sum_q WfT[q][o]*F[q][b][p] + fc[o]).
// Grid: 8 b * 200 p-tiles = 1600 blocks x 256 threads.
// Block tile: 128 o x 128 p, K in 32 phases of 16 q.
// Thread tile: 8 o x 8 p (acc[8][4] p-paired float2).
// ---------------------------------------------------------------------------
__global__ void __launch_bounds__(256) fus_kernel(float* __restrict__ out) {
    int bx = blockIdx.x;            // 1600
    int b  = bx / 200;
    int p0 = (bx % 200) * 128;
    int t  = threadIdx.x;
    int lane = t & 31, warp = t >> 5;
    int wo = warp & 1, wp = warp >> 1;     // o-half, p-quarter
    int lo = lane & 7, lp = lane >> 3;     // o-oct, p-oct
    int ob = wo * 64 + lo * 8;
    int pb = wp * 32 + lp * 8;

    __shared__ __align__(16) float Fs[16 * 128];
    __shared__ __align__(16) float Ws[16 * 128];

    float2 acc[8][4];
#pragma unroll
    for (int oi = 0; oi < 8; ++oi)
#pragma unroll
        for (int pi = 0; pi < 4; ++pi) acc[oi][pi] = make_float2(0.f, 0.f);

    for (int phase = 0; phase < 32; ++phase) {
        int q0 = phase * 16;
#pragma unroll
        for (int i = 0; i < 2; ++i) {
            int fl = i * 256 + t;          // 0..511
            int q  = fl >> 5;              // 0..15
            int pq = fl & 31;              // float4 slot
            int qq = q0 + q;
            int dirq = qq >> 7, cc = qq & 127;
            const float* fp = (dirq < 2)
                ? (g_feat + ((size_t)(dirq * 8 + b) * 128 + cc) * SPAT)
                : (g_tmp  + ((size_t)((dirq - 2) * 8 + b) * 128 + cc) * SPAT);
            *reinterpret_cast<float4*>(&Fs[q * 128 + pq * 4]) =
                *reinterpret_cast<const float4*>(fp + p0 + pq * 4);
            *reinterpret_cast<float4*>(&Ws[q * 128 + pq * 4]) =
                *reinterpret_cast<const float4*>(g_wfT + (size_t)qq * 128 + pq * 4);
        }
        __syncthreads();

#pragma unroll
        for (int q = 0; q < 16; ++q) {
            float4 W0 = *reinterpret_cast<const float4*>(&Ws[q * 128 + ob]);
            float4 W1 = *reinterpret_cast<const float4*>(&Ws[q * 128 + ob + 4]);
            float4 V0 = *reinterpret_cast<const float4*>(&Fs[q * 128 + pb]);
            float4 V1 = *reinterpret_cast<const float4*>(&Fs[q * 128 + pb + 4]);
            float2 vp[4] = { lo2(V0), hi2(V0), lo2(V1), hi2(V1) };
            float wv[8] = { W0.x, W0.y, W0.z, W0.w, W1.x, W1.y, W1.z, W1.w };
#pragma unroll
            for (int oi = 0; oi < 8; ++oi) {
                float2 ws = make_float2(wv[oi], wv[oi]);
#pragma unroll
                for (int pi = 0; pi < 4; ++pi)
                    acc[oi][pi] = ffma2f(vp[pi], ws, acc[oi][pi]);
            }
        }
        __syncthreads();
    }

#pragma unroll
    for (int oi = 0; oi < 8; ++oi) {
        int o = ob + oi;
        float c = g_fc[o];
        float* dst = out + ((size_t)b * 128 + o) * SPAT + p0 + pb;
        float4 r0, r1;
        r0.x = fmaxf(acc[oi][0].x + c, 0.f);
        r0.y = fmaxf(acc[oi][0].y + c, 0.f);
        r0.z = fmaxf(acc[oi][1].x + c, 0.f);
        r0.w = fmaxf(acc[oi][1].y + c, 0.f);
        r1.x = fmaxf(acc[oi][2].x + c, 0.f);
        r1.y = fmaxf(acc[oi][2].y + c, 0.f);
        r1.z = fmaxf(acc[oi][3].x + c, 0.f);
        r1.w = fmaxf(acc[oi][3].y + c, 0.f);
        *reinterpret_cast<float4*>(dst)     = r0;
        *reinterpret_cast<float4*>(dst + 4) = r1;
    }
}

// ---------------------------------------------------------------------------
extern "C" void kernel_launch(void* const* d_in, const int* in_sizes, int n_in,
                              void* d_out, int out_size) {
    const float* x         = (const float*)d_in[0];
    const float* kernels   = (const float*)d_in[1];
    const float* biases    = (const float*)d_in[2];
    const float* bn_gamma  = (const float*)d_in[3];
    const float* bn_beta   = (const float*)d_in[4];
    const float* bn_mean   = (const float*)d_in[5];
    const float* bn_var    = (const float*)d_in[6];
    const float* prelu_a   = (const float*)d_in[7];
    const float* fus_w     = (const float*)d_in[8];
    const float* fus_b     = (const float*)d_in[9];
    const float* fbn_gamma = (const float*)d_in[10];
    const float* fbn_beta  = (const float*)d_in[11];
    const float* fbn_mean  = (const float*)d_in[12];
    const float* fbn_var   = (const float*)d_in[13];

    // our idx 0..2 below; harness prefix = 2 -> ncu -s 5 captures our idx 3 = pre
    prep_kernel<<<128, 256>>>(kernels, bn_gamma, bn_beta, bn_mean, bn_var,
                              fus_w, fus_b, fbn_gamma, fbn_beta, fbn_mean, fbn_var);

    transpose_kernel<<<8 * 128 * 25, dim3(32, 8)>>>(x, 0);

    noop_kernel<<<1, 32>>>();

    pre_kernel<<<25600, 256>>>(x, biases);

    // 40 fused recurrence launches; each advances all dirs/batches by 4 lines
    for (int g = 0; g < 40; ++g)
        step4_kernel<<<320, 128>>>(prelu_a, g);

    // bring dirs 2,3 back to canonical [h][w] layout for fusion
    transpose_kernel<<<2 * 8 * 128 * 25, dim3(32, 8)>>>(x, 1);

    // fused 1x1 conv + BN + ReLU (register-tiled GEMM)
    fus_kernel<<<1600, 256>>>((float*)d_out);
}